// round 1
// baseline (speedup 1.0000x reference)
#include <cuda_runtime.h>
#include <math.h>

// ---------------- problem constants ----------------
#define BATCH   2
#define TT      4096
#define BT      8192            // BATCH * TT
#define NQ      256
#define NAUX    28
#define NR      512
#define NS      256
#define NLAYERS 30

// ---------------- GEMM tiling ----------------
#define BM 128
#define BN 128
#define BK 16
#define NTHREADS 256

// ---------------- device scratch (no allocations allowed) ----------------
__device__ float d_res [NR * BT];                    // residual activations (512 x 8192)
__device__ float d_g   [NR * BT];                    // gated activations    (512 x 8192)
__device__ float d_skip[NS * BT];                    // skip accumulator / o2 (256 x 8192)

__device__ float d_Wg [NLAYERS * 2 * NR * 1024];     // [l][tap][k=i][m] m: 128*(c/64)+64*half+c%64
__device__ float d_Wa [NLAYERS * NAUX * 1024];       // [l][a][m]
__device__ float d_Wrs[NLAYERS * NR * 768];          // [l][k=i][m] m<256 skip, else res
__device__ float d_bg [NLAYERS * 1024];
__device__ float d_brs[NLAYERS * 768];
__device__ float d_Wp1[NS * NS];                     // [k][m] = post1_w[m][k]
__device__ float d_Wp2[NS * NQ];                     // [k][m] = post2_w[m][k]
__device__ float d_Wp3[NQ * NQ];                     // [k][m] = lin_w[m][k]

// =====================================================================
// Packing kernels (run every launch; deterministic; ~250MB traffic total)
// =====================================================================
__global__ void pack_gate_k(const float* __restrict__ ws, const float* __restrict__ wt) {
    int idx = blockIdx.x * blockDim.x + threadIdx.x;
    if (idx >= NLAYERS * 2 * NR * 1024) return;
    int m   = idx & 1023;
    int r   = idx >> 10;
    int i   = r & 511;
    int r2  = r >> 9;
    int tap = r2 & 1;
    int l   = r2 >> 1;
    int half = (m >> 6) & 1;
    int c    = ((m >> 7) << 6) | (m & 63);
    const float* src = half ? wt : ws;
    d_Wg[idx] = src[((l * NR + c) * NR + i) * 2 + tap];
}

__global__ void pack_aux_k(const float* __restrict__ as_, const float* __restrict__ at_) {
    int idx = blockIdx.x * blockDim.x + threadIdx.x;
    if (idx >= NLAYERS * NAUX * 1024) return;
    int m = idx & 1023;
    int r = idx >> 10;
    int a = r % NAUX;
    int l = r / NAUX;
    int half = (m >> 6) & 1;
    int c    = ((m >> 7) << 6) | (m & 63);
    const float* src = half ? at_ : as_;
    d_Wa[idx] = src[(l * NR + c) * NAUX + a];
}

__global__ void pack_rs_k(const float* __restrict__ sw, const float* __restrict__ rw) {
    int idx = blockIdx.x * blockDim.x + threadIdx.x;
    if (idx >= NLAYERS * NR * 768) return;
    int l   = idx / (NR * 768);
    int rem = idx - l * (NR * 768);
    int k   = rem / 768;
    int m   = rem % 768;
    d_Wrs[idx] = (m < 256) ? sw[(l * NS + m) * NR + k]
                           : rw[(l * NR + (m - 256)) * NR + k];
}

__global__ void pack_bias_k(const float* __restrict__ dsb, const float* __restrict__ dtb,
                            const float* __restrict__ asb, const float* __restrict__ atb,
                            const float* __restrict__ skb, const float* __restrict__ reb) {
    int idx = blockIdx.x * blockDim.x + threadIdx.x;
    if (idx < NLAYERS * 1024) {
        int l = idx >> 10;
        int m = idx & 1023;
        int half = (m >> 6) & 1;
        int c    = ((m >> 7) << 6) | (m & 63);
        d_bg[idx] = half ? (dtb[l * NR + c] + atb[l * NR + c])
                         : (dsb[l * NR + c] + asb[l * NR + c]);
    } else if (idx < NLAYERS * 1024 + NLAYERS * 768) {
        int j = idx - NLAYERS * 1024;
        int l = j / 768;
        int m = j % 768;
        d_brs[j] = (m < 256) ? skb[l * NS + m] : reb[l * NR + (m - 256)];
    }
}

__global__ void pack_post_k(const float* __restrict__ p1, const float* __restrict__ p2,
                            const float* __restrict__ p3) {
    int idx = blockIdx.x * blockDim.x + threadIdx.x;
    if (idx >= 3 * 65536) return;
    int w = idx >> 16;
    int r = idx & 65535;
    int k = r >> 8;
    int m = r & 255;
    float v;
    if (w == 0)      { v = p1[m * 256 + k]; d_Wp1[r] = v; }
    else if (w == 1) { v = p2[m * 256 + k]; d_Wp2[r] = v; }
    else             { v = p3[m * 256 + k]; d_Wp3[r] = v; }
}

__global__ void zero_skip_k() {
    int idx = blockIdx.x * blockDim.x + threadIdx.x;
    if (idx < NS * BT) d_skip[idx] = 0.f;
}

// =====================================================================
// Embedding: one-hot + causal conv (K=2, d=1) == table lookup
// out[c, b*T+t] = W[c, x[t-1], 0] + W[c, x[t], 1] + b[c]
// =====================================================================
__global__ void embed_k(const int* __restrict__ x, const float* __restrict__ cw,
                        const float* __restrict__ cb) {
    int j = blockIdx.x * blockDim.x + threadIdx.x;   // 0..8191
    int c = blockIdx.y;                              // 0..511
    if (j >= BT) return;
    int b = j >> 12;
    int t = j & (TT - 1);
    int q1 = x[b * TT + t] & 255;
    float v = cw[(c * NQ + q1) * 2 + 1] + cb[c];
    if (t > 0) {
        int q0 = x[b * TT + t - 1] & 255;
        v += cw[(c * NQ + q0) * 2 + 0];
    }
    d_res[c * BT + j] = v;
}

// =====================================================================
// Gate GEMM: M=1024 (sig/tanh interleaved per 128-row group), N=4096/batch
// K segments: 512 (tap0, shifted by d), 512 (tap1), 28 (aux on h)
// Epilogue: g = sigmoid(s) * tanh(t)
// =====================================================================
__global__ __launch_bounds__(NTHREADS)
void gate_k(int l, int d, const float* __restrict__ h) {
    __shared__ float As[BK][BM];
    __shared__ float Bs[BK][BN];

    int tid = threadIdx.x;
    int tx  = tid & 15;      // column group (8 cols)
    int ty  = tid >> 4;      // row group (4+4 rows)
    int mb  = blockIdx.x;    // 0..7 : channels [mb*64, mb*64+64)
    int t0  = blockIdx.y * BN;
    int z   = blockIdx.z;

    const float* resB = d_res + z * TT;        // row stride BT
    const float* hB   = h + z * NAUX * TT;     // row stride TT

    float acc[8][8];
    #pragma unroll
    for (int i = 0; i < 8; ++i)
        #pragma unroll
        for (int j = 0; j < 8; ++j) acc[i][j] = 0.f;

    #pragma unroll 1
    for (int seg = 0; seg < 3; ++seg) {
        int Kseg = (seg < 2) ? NR : NAUX;
        const float* Aseg = (seg < 2)
            ? (d_Wg + (size_t)(l * 2 + seg) * NR * 1024)
            : (d_Wa + (size_t)l * NAUX * 1024);

        for (int kt = 0; kt < Kseg; kt += BK) {
            // ---- load A tile (BK x BM) ----
            #pragma unroll
            for (int p = 0; p < 8; ++p) {
                int e = tid + p * 256;
                int k = e >> 7;
                int m = e & 127;
                int kg = kt + k;
                float v = 0.f;
                if (kg < Kseg) v = Aseg[(size_t)kg * 1024 + mb * 128 + m];
                As[k][m] = v;
            }
            // ---- load B tile (BK x BN) ----
            #pragma unroll
            for (int p = 0; p < 8; ++p) {
                int e = tid + p * 256;
                int k = e >> 7;
                int n = e & 127;
                int kg = kt + k;
                int tc = t0 + n;
                float v = 0.f;
                if (seg == 0) {
                    if (tc >= d) v = resB[(size_t)kg * BT + tc - d];
                } else if (seg == 1) {
                    v = resB[(size_t)kg * BT + tc];
                } else {
                    if (kg < NAUX) v = hB[(size_t)kg * TT + tc];
                }
                Bs[k][n] = v;
            }
            __syncthreads();

            #pragma unroll
            for (int kk = 0; kk < BK; ++kk) {
                float a[8], b[8];
                #pragma unroll
                for (int i = 0; i < 4; ++i) {
                    a[i]     = As[kk][ty * 4 + i];
                    a[4 + i] = As[kk][64 + ty * 4 + i];
                }
                #pragma unroll
                for (int j = 0; j < 8; ++j) b[j] = Bs[kk][tx * 8 + j];
                #pragma unroll
                for (int i = 0; i < 8; ++i)
                    #pragma unroll
                    for (int j = 0; j < 8; ++j)
                        acc[i][j] = fmaf(a[i], b[j], acc[i][j]);
            }
            __syncthreads();
        }
    }

    // ---- gated activation epilogue ----
    const float* bgp = d_bg + l * 1024 + mb * 128;
    int colbase = z * TT + t0 + tx * 8;
    #pragma unroll
    for (int i = 0; i < 4; ++i) {
        int c = mb * 64 + ty * 4 + i;
        float bs = bgp[ty * 4 + i];
        float bt = bgp[64 + ty * 4 + i];
        float gv[8];
        #pragma unroll
        for (int j = 0; j < 8; ++j) {
            float sv = acc[i][j] + bs;
            float tv = acc[4 + i][j] + bt;
            float sg = __fdividef(1.f, 1.f + __expf(-sv));
            float e2 = __expf(2.f * tv);
            float th = 1.f - __fdividef(2.f, e2 + 1.f);
            gv[j] = sg * th;
        }
        float4 v0 = make_float4(gv[0], gv[1], gv[2], gv[3]);
        float4 v1 = make_float4(gv[4], gv[5], gv[6], gv[7]);
        *(float4*)&d_g[(size_t)c * BT + colbase]     = v0;
        *(float4*)&d_g[(size_t)c * BT + colbase + 4] = v1;
    }
}

// =====================================================================
// Skip/Res GEMM: M=768 (rows 0..255 skip, 256..767 res), K=512 over g
// Epilogue: skip += acc + b ; res(out) += acc + b
// =====================================================================
__global__ __launch_bounds__(NTHREADS)
void skipres_k(int l) {
    __shared__ float As[BK][BM];
    __shared__ float Bs[BK][BN];

    int tid = threadIdx.x;
    int tx  = tid & 15;
    int ty  = tid >> 4;
    int mb  = blockIdx.x;    // 0..5
    int t0  = blockIdx.y * BN;
    int z   = blockIdx.z;

    const float* gB = d_g + z * TT;
    const float* Al = d_Wrs + (size_t)l * NR * 768;

    float acc[8][8];
    #pragma unroll
    for (int i = 0; i < 8; ++i)
        #pragma unroll
        for (int j = 0; j < 8; ++j) acc[i][j] = 0.f;

    for (int kt = 0; kt < NR; kt += BK) {
        #pragma unroll
        for (int p = 0; p < 8; ++p) {
            int e = tid + p * 256;
            int k = e >> 7;
            int m = e & 127;
            As[k][m] = Al[(size_t)(kt + k) * 768 + mb * 128 + m];
        }
        #pragma unroll
        for (int p = 0; p < 8; ++p) {
            int e = tid + p * 256;
            int k = e >> 7;
            int n = e & 127;
            Bs[k][n] = gB[(size_t)(kt + k) * BT + t0 + n];
        }
        __syncthreads();
        #pragma unroll
        for (int kk = 0; kk < BK; ++kk) {
            float a[8], b[8];
            #pragma unroll
            for (int i = 0; i < 4; ++i) {
                a[i]     = As[kk][ty * 4 + i];
                a[4 + i] = As[kk][64 + ty * 4 + i];
            }
            #pragma unroll
            for (int j = 0; j < 8; ++j) b[j] = Bs[kk][tx * 8 + j];
            #pragma unroll
            for (int i = 0; i < 8; ++i)
                #pragma unroll
                for (int j = 0; j < 8; ++j)
                    acc[i][j] = fmaf(a[i], b[j], acc[i][j]);
        }
        __syncthreads();
    }

    int colbase = z * TT + t0 + tx * 8;
    #pragma unroll
    for (int i = 0; i < 8; ++i) {
        int r  = (i < 4) ? (ty * 4 + i) : (64 + ty * 4 + (i - 4));
        int mg = mb * 128 + r;
        float bias = d_brs[l * 768 + mg];
        float* dst = (mg < 256) ? &d_skip[(size_t)mg * BT + colbase]
                                : &d_res[(size_t)(mg - 256) * BT + colbase];
        float4 o0 = *(float4*)dst;
        float4 o1 = *(float4*)(dst + 4);
        o0.x += acc[i][0] + bias; o0.y += acc[i][1] + bias;
        o0.z += acc[i][2] + bias; o0.w += acc[i][3] + bias;
        o1.x += acc[i][4] + bias; o1.y += acc[i][5] + bias;
        o1.z += acc[i][6] + bias; o1.w += acc[i][7] + bias;
        *(float4*)dst       = o0;
        *(float4*)(dst + 4) = o1;
    }
}

// =====================================================================
// Post GEMMs (M=256, N=8192, K=256)
// mode 1: o1 = relu(post1 @ relu(skip) + b)       -> d_g
// mode 2: o2 = post2 @ o1 + b                      -> d_skip
// mode 3: out[j][q] = lin @ o2 + lin_b (transposed store to d_out)
// =====================================================================
__global__ __launch_bounds__(NTHREADS)
void post_k(int mode, const float* __restrict__ bias, float* __restrict__ outp) {
    __shared__ float As[BK][BM];
    __shared__ float Bs[BK][BN];

    int tid = threadIdx.x;
    int tx  = tid & 15;
    int ty  = tid >> 4;
    int mb  = blockIdx.x;     // 0..1
    int j0  = blockIdx.y * BN;

    const float* A    = (mode == 1) ? d_Wp1 : (mode == 2) ? d_Wp2 : d_Wp3;
    const float* Bsrc = (mode == 2) ? d_g : d_skip;

    float acc[8][8];
    #pragma unroll
    for (int i = 0; i < 8; ++i)
        #pragma unroll
        for (int j = 0; j < 8; ++j) acc[i][j] = 0.f;

    for (int kt = 0; kt < 256; kt += BK) {
        #pragma unroll
        for (int p = 0; p < 8; ++p) {
            int e = tid + p * 256;
            int k = e >> 7;
            int m = e & 127;
            As[k][m] = A[(size_t)(kt + k) * 256 + mb * 128 + m];
        }
        #pragma unroll
        for (int p = 0; p < 8; ++p) {
            int e = tid + p * 256;
            int k = e >> 7;
            int n = e & 127;
            float v = Bsrc[(size_t)(kt + k) * BT + j0 + n];
            if (mode == 1) v = fmaxf(v, 0.f);
            Bs[k][n] = v;
        }
        __syncthreads();
        #pragma unroll
        for (int kk = 0; kk < BK; ++kk) {
            float a[8], b[8];
            #pragma unroll
            for (int i = 0; i < 4; ++i) {
                a[i]     = As[kk][ty * 4 + i];
                a[4 + i] = As[kk][64 + ty * 4 + i];
            }
            #pragma unroll
            for (int j = 0; j < 8; ++j) b[j] = Bs[kk][tx * 8 + j];
            #pragma unroll
            for (int i = 0; i < 8; ++i)
                #pragma unroll
                for (int j = 0; j < 8; ++j)
                    acc[i][j] = fmaf(a[i], b[j], acc[i][j]);
        }
        __syncthreads();
    }

    int colbase = j0 + tx * 8;
    #pragma unroll
    for (int i = 0; i < 8; ++i) {
        int r  = (i < 4) ? (ty * 4 + i) : (64 + ty * 4 + (i - 4));
        int mg = mb * 128 + r;
        float bv = bias[mg];
        if (mode == 3) {
            #pragma unroll
            for (int j = 0; j < 8; ++j)
                outp[(size_t)(colbase + j) * NQ + mg] = acc[i][j] + bv;
        } else {
            float ov[8];
            #pragma unroll
            for (int j = 0; j < 8; ++j) {
                float v = acc[i][j] + bv;
                if (mode == 1) v = fmaxf(v, 0.f);
                ov[j] = v;
            }
            float* dst = (mode == 1) ? &d_g[(size_t)mg * BT + colbase]
                                     : &d_skip[(size_t)mg * BT + colbase];
            *(float4*)dst       = make_float4(ov[0], ov[1], ov[2], ov[3]);
            *(float4*)(dst + 4) = make_float4(ov[4], ov[5], ov[6], ov[7]);
        }
    }
}

// =====================================================================
// Launch
// =====================================================================
extern "C" void kernel_launch(void* const* d_in, const int* in_sizes, int n_in,
                              void* d_out, int out_size) {
    const int*   x          = (const int*)  d_in[0];
    const float* h          = (const float*)d_in[1];
    const float* causal_w   = (const float*)d_in[2];
    const float* causal_b   = (const float*)d_in[3];
    const float* dil_sig_w  = (const float*)d_in[4];
    const float* dil_sig_b  = (const float*)d_in[5];
    const float* dil_tanh_w = (const float*)d_in[6];
    const float* dil_tanh_b = (const float*)d_in[7];
    const float* aux_sig_w  = (const float*)d_in[8];
    const float* aux_sig_b  = (const float*)d_in[9];
    const float* aux_tanh_w = (const float*)d_in[10];
    const float* aux_tanh_b = (const float*)d_in[11];
    const float* skip_w     = (const float*)d_in[12];
    const float* skip_b     = (const float*)d_in[13];
    const float* res_w      = (const float*)d_in[14];
    const float* res_b      = (const float*)d_in[15];
    const float* post1_w    = (const float*)d_in[16];
    const float* post1_b    = (const float*)d_in[17];
    const float* post2_w    = (const float*)d_in[18];
    const float* post2_b    = (const float*)d_in[19];
    const float* lin_w      = (const float*)d_in[20];
    const float* lin_b      = (const float*)d_in[21];

    // --- repack weights into GEMM-friendly layouts ---
    {
        int n = NLAYERS * 2 * NR * 1024;
        pack_gate_k<<<(n + 255) / 256, 256>>>(dil_sig_w, dil_tanh_w);
    }
    {
        int n = NLAYERS * NAUX * 1024;
        pack_aux_k<<<(n + 255) / 256, 256>>>(aux_sig_w, aux_tanh_w);
    }
    {
        int n = NLAYERS * NR * 768;
        pack_rs_k<<<(n + 255) / 256, 256>>>(skip_w, res_w);
    }
    {
        int n = NLAYERS * 1024 + NLAYERS * 768;
        pack_bias_k<<<(n + 255) / 256, 256>>>(dil_sig_b, dil_tanh_b,
                                              aux_sig_b, aux_tanh_b,
                                              skip_b, res_b);
    }
    {
        int n = 3 * 65536;
        pack_post_k<<<(n + 255) / 256, 256>>>(post1_w, post2_w, lin_w);
    }

    // --- init ---
    zero_skip_k<<<(NS * BT + 255) / 256, 256>>>();
    embed_k<<<dim3(BT / 256, NR), 256>>>(x, causal_w, causal_b);

    // --- 30 residual layers ---
    for (int l = 0; l < NLAYERS; ++l) {
        int d = 1 << (l % 10);
        gate_k<<<dim3(8, TT / BN, BATCH), NTHREADS>>>(l, d, h);
        skipres_k<<<dim3(6, TT / BN, BATCH), NTHREADS>>>(l);
    }

    // --- postnet ---
    post_k<<<dim3(2, BT / BN), NTHREADS>>>(1, post1_b, nullptr);
    post_k<<<dim3(2, BT / BN), NTHREADS>>>(2, post2_b, nullptr);
    post_k<<<dim3(2, BT / BN), NTHREADS>>>(3, lin_b, (float*)d_out);
}

// round 3
// speedup vs baseline: 1.2280x; 1.2280x over previous
#include <cuda_runtime.h>
#include <math.h>
#include <stdint.h>

// ---------------- problem constants ----------------
#define BATCH   2
#define TT      4096
#define BT      8192
#define NQ      256
#define NAUX    28
#define NR      512
#define NS      256
#define NLAYERS 30

// ---------------- GEMM tiling ----------------
#define BM 128
#define BN 64
#define BKK 32
#define LDA2 (BM + 4)       // A smem row stride in float2 units (132*8B: conflict-free)
#define LDB  (BN + 8)       // B smem row stride in floats (72: banks 8k+c all distinct)
#define NTHREADS 256

// ---------------- device scratch ----------------
__device__ float d_res [NR * BT];
__device__ float d_g   [NR * BT];
__device__ float d_skip[NS * BT];

// weights pre-split into (hi, lo) tf32 pairs
__device__ float2 d_Wg2 [NLAYERS * 2 * NR * 1024];   // [l][tap][k][m] gate-interleaved m
__device__ float2 d_Wa2 [NLAYERS * NAUX * 1024];
__device__ float2 d_Wrs2[NLAYERS * NR * 768];
__device__ float2 d_Wp12[NS * NS];
__device__ float2 d_Wp22[NS * NQ];
__device__ float2 d_Wp32[NQ * NQ];
__device__ float  d_bg  [NLAYERS * 1024];
__device__ float  d_brs [NLAYERS * 768];

__device__ __forceinline__ uint32_t f2tf32(float x) {
    uint32_t u;
    asm("cvt.rna.tf32.f32 %0, %1;" : "=r"(u) : "f"(x));
    return u;
}

__device__ __forceinline__ float2 split_tf32(float x) {
    uint32_t hi = f2tf32(x);
    float hif = __uint_as_float(hi);
    uint32_t lo = f2tf32(x - hif);
    return make_float2(hif, __uint_as_float(lo));
}

__device__ __forceinline__ void mma8(float* c, const uint32_t* a, const uint32_t* b) {
    asm volatile(
        "mma.sync.aligned.m16n8k8.row.col.f32.tf32.tf32.f32 "
        "{%0,%1,%2,%3}, {%4,%5,%6,%7}, {%8,%9}, {%0,%1,%2,%3};\n"
        : "+f"(c[0]), "+f"(c[1]), "+f"(c[2]), "+f"(c[3])
        : "r"(a[0]), "r"(a[1]), "r"(a[2]), "r"(a[3]), "r"(b[0]), "r"(b[1]));
}

// gate row interleave: within a 128-row block, channel cc (0..63) has
// sig at row 16*(cc/8)+cc%8 and tanh at +8.
__device__ __forceinline__ int gate_channel_of_row(int mlocal) {
    return ((mlocal >> 4) << 3) | (mlocal & 7);
}

// =====================================================================
// Packing kernels (split weights to tf32 hi/lo)
// =====================================================================
__global__ void pack_gate_k(const float* __restrict__ ws, const float* __restrict__ wt) {
    int idx = blockIdx.x * blockDim.x + threadIdx.x;
    if (idx >= NLAYERS * 2 * NR * 1024) return;
    int m   = idx & 1023;
    int r   = idx >> 10;
    int i   = r & 511;
    int r2  = r >> 9;
    int tap = r2 & 1;
    int l   = r2 >> 1;
    int mlocal = m & 127;
    int half   = (mlocal >> 3) & 1;
    int cc     = gate_channel_of_row(mlocal & ~8);
    int c      = (m >> 7) * 64 + cc;
    const float* src = half ? wt : ws;
    d_Wg2[idx] = split_tf32(src[((l * NR + c) * NR + i) * 2 + tap]);
}

__global__ void pack_aux_k(const float* __restrict__ as_, const float* __restrict__ at_) {
    int idx = blockIdx.x * blockDim.x + threadIdx.x;
    if (idx >= NLAYERS * NAUX * 1024) return;
    int m = idx & 1023;
    int r = idx >> 10;
    int a = r % NAUX;
    int l = r / NAUX;
    int mlocal = m & 127;
    int half   = (mlocal >> 3) & 1;
    int cc     = gate_channel_of_row(mlocal & ~8);
    int c      = (m >> 7) * 64 + cc;
    const float* src = half ? at_ : as_;
    d_Wa2[idx] = split_tf32(src[(l * NR + c) * NAUX + a]);
}

__global__ void pack_rs_k(const float* __restrict__ sw, const float* __restrict__ rw) {
    int idx = blockIdx.x * blockDim.x + threadIdx.x;
    if (idx >= NLAYERS * NR * 768) return;
    int l   = idx / (NR * 768);
    int rem = idx - l * (NR * 768);
    int k   = rem / 768;
    int m   = rem % 768;
    float v = (m < 256) ? sw[(l * NS + m) * NR + k]
                        : rw[(l * NR + (m - 256)) * NR + k];
    d_Wrs2[idx] = split_tf32(v);
}

__global__ void pack_bias_k(const float* __restrict__ dsb, const float* __restrict__ dtb,
                            const float* __restrict__ asb, const float* __restrict__ atb,
                            const float* __restrict__ skb, const float* __restrict__ reb) {
    int idx = blockIdx.x * blockDim.x + threadIdx.x;
    if (idx < NLAYERS * 1024) {
        int l = idx >> 10;
        int m = idx & 1023;
        int mlocal = m & 127;
        int half   = (mlocal >> 3) & 1;
        int cc     = gate_channel_of_row(mlocal & ~8);
        int c      = (m >> 7) * 64 + cc;
        d_bg[idx] = half ? (dtb[l * NR + c] + atb[l * NR + c])
                         : (dsb[l * NR + c] + asb[l * NR + c]);
    } else if (idx < NLAYERS * 1024 + NLAYERS * 768) {
        int j = idx - NLAYERS * 1024;
        int l = j / 768;
        int m = j % 768;
        d_brs[j] = (m < 256) ? skb[l * NS + m] : reb[l * NR + (m - 256)];
    }
}

__global__ void pack_post_k(const float* __restrict__ p1, const float* __restrict__ p2,
                            const float* __restrict__ p3) {
    int idx = blockIdx.x * blockDim.x + threadIdx.x;
    if (idx >= 3 * 65536) return;
    int w = idx >> 16;
    int r = idx & 65535;
    int k = r >> 8;
    int m = r & 255;
    if (w == 0)      d_Wp12[r] = split_tf32(p1[m * 256 + k]);
    else if (w == 1) d_Wp22[r] = split_tf32(p2[m * 256 + k]);
    else             d_Wp32[r] = split_tf32(p3[m * 256 + k]);
}

__global__ void zero_skip_k() {
    int idx = blockIdx.x * blockDim.x + threadIdx.x;
    if (idx < NS * BT) d_skip[idx] = 0.f;
}

// =====================================================================
// Embedding (table lookup)
// =====================================================================
__global__ void embed_k(const int* __restrict__ x, const float* __restrict__ cw,
                        const float* __restrict__ cb) {
    int j = blockIdx.x * blockDim.x + threadIdx.x;
    int c = blockIdx.y;
    if (j >= BT) return;
    int b = j >> 12;
    int t = j & (TT - 1);
    int q1 = x[b * TT + t] & 255;
    float v = cw[(c * NQ + q1) * 2 + 1] + cb[c];
    if (t > 0) {
        int q0 = x[b * TT + t - 1] & 255;
        v += cw[(c * NQ + q0) * 2 + 0];
    }
    d_res[c * BT + j] = v;
}

// =====================================================================
// 3xTF32 MMA compute over one (BKK x BM hi/lo) / (BKK x BN fp32) tile pair
// acc[4][2][4]; warp tile 64(m) x 16(n)
// =====================================================================
#define MMA_COMPUTE3(acc, As2, Bs, warp_m, warp_n, lane)                        \
    do {                                                                        \
        _Pragma("unroll")                                                       \
        for (int ks = 0; ks < 4; ++ks) {                                        \
            int cA = (ks << 3) + ((lane) & 3);                                  \
            int nb = (warp_n) * 16 + ((lane) >> 2);                             \
            uint32_t bh[2][2], bl[2][2];                                        \
            _Pragma("unroll")                                                   \
            for (int nt = 0; nt < 2; ++nt) {                                    \
                float b0 = Bs[cA][nb + nt * 8];                                 \
                float b1 = Bs[cA + 4][nb + nt * 8];                             \
                bh[nt][0] = f2tf32(b0);                                         \
                bl[nt][0] = f2tf32(b0 - __uint_as_float(bh[nt][0]));            \
                bh[nt][1] = f2tf32(b1);                                         \
                bl[nt][1] = f2tf32(b1 - __uint_as_float(bh[nt][1]));            \
            }                                                                   \
            int rb = (warp_m) * 64 + ((lane) >> 2);                             \
            _Pragma("unroll")                                                   \
            for (int mt = 0; mt < 4; ++mt) {                                    \
                int r = rb + mt * 16;                                           \
                float2 a0 = As2[cA][r];                                         \
                float2 a1 = As2[cA][r + 8];                                     \
                float2 a2 = As2[cA + 4][r];                                     \
                float2 a3 = As2[cA + 4][r + 8];                                 \
                uint32_t ah[4] = { __float_as_uint(a0.x), __float_as_uint(a1.x),\
                                   __float_as_uint(a2.x), __float_as_uint(a3.x)};\
                uint32_t al[4] = { __float_as_uint(a0.y), __float_as_uint(a1.y),\
                                   __float_as_uint(a2.y), __float_as_uint(a3.y)};\
                _Pragma("unroll")                                               \
                for (int nt = 0; nt < 2; ++nt) {                                \
                    mma8(acc[mt][nt], ah, bh[nt]);                              \
                    mma8(acc[mt][nt], ah, bl[nt]);                              \
                    mma8(acc[mt][nt], al, bh[nt]);                              \
                }                                                               \
            }                                                                   \
        }                                                                       \
    } while (0)

// =====================================================================
// Gate GEMM: M=1024, N per batch 4096, K = 512 + 512 + 28
// =====================================================================
__global__ __launch_bounds__(NTHREADS, 2)
void gate_k(int l, int d, const float* __restrict__ h) {
    __shared__ float2 As2[BKK][LDA2];
    __shared__ float  Bs [BKK][LDB];

    int tid    = threadIdx.x;
    int lane   = tid & 31;
    int wid    = tid >> 5;
    int warp_m = wid & 1;
    int warp_n = wid >> 1;          // 0..3
    int mb     = blockIdx.x;        // 0..7
    int t0     = blockIdx.y * BN;
    int z      = blockIdx.z;

    const float* resB = d_res + (size_t)z * TT;
    const float* hB   = h + (size_t)z * NAUX * TT;

    float acc[4][2][4] = {};

    #pragma unroll 1
    for (int seg = 0; seg < 3; ++seg) {
        int Kseg = (seg < 2) ? NR : NAUX;
        const float2* Aseg = (seg < 2)
            ? (d_Wg2 + (size_t)(l * 2 + seg) * NR * 1024)
            : (d_Wa2 + (size_t)l * NAUX * 1024);

        for (int kt = 0; kt < Kseg; kt += BKK) {
            // A tile: 32 x 128 float2 = 2048 float4
            #pragma unroll
            for (int p = 0; p < 8; ++p) {
                int e  = tid + p * 256;
                int k  = e >> 6;
                int m2 = (e & 63) << 1;
                float4 v = make_float4(0.f, 0.f, 0.f, 0.f);
                if (kt + k < Kseg)
                    v = *(const float4*)&Aseg[(size_t)(kt + k) * 1024 + mb * 128 + m2];
                *(float4*)&As2[k][m2] = v;
            }
            // B tile: 32 x 64 floats = 512 float4
            #pragma unroll
            for (int p = 0; p < 2; ++p) {
                int e  = tid + p * 256;
                int k  = e >> 4;
                int n4 = (e & 15) << 2;
                float4 v = make_float4(0.f, 0.f, 0.f, 0.f);
                if (seg == 0) {
                    int col = t0 + n4 - d;
                    if ((d & 3) == 0) {
                        if (col >= 0)
                            v = *(const float4*)&resB[(size_t)(kt + k) * BT + col];
                    } else {
                        const float* row = &resB[(size_t)(kt + k) * BT];
                        float tmp[4];
                        #pragma unroll
                        for (int j = 0; j < 4; ++j)
                            tmp[j] = (col + j >= 0) ? row[col + j] : 0.f;
                        v = make_float4(tmp[0], tmp[1], tmp[2], tmp[3]);
                    }
                } else if (seg == 1) {
                    v = *(const float4*)&resB[(size_t)(kt + k) * BT + t0 + n4];
                } else {
                    if (kt + k < NAUX)
                        v = *(const float4*)&hB[(size_t)(kt + k) * TT + t0 + n4];
                }
                *(float4*)&Bs[k][n4] = v;
            }
            __syncthreads();
            MMA_COMPUTE3(acc, As2, Bs, warp_m, warp_n, lane);
            __syncthreads();
        }
    }

    // gated activation epilogue
    const float* bgp = d_bg + l * 1024 + mb * 128;
    int colbase = z * TT + t0 + warp_n * 16 + (lane & 3) * 2;
    #pragma unroll
    for (int mt = 0; mt < 4; ++mt) {
        int r  = warp_m * 64 + mt * 16 + (lane >> 2);
        int cc = gate_channel_of_row(r);
        int cg = mb * 64 + cc;
        float bs = bgp[r];
        float bt = bgp[r + 8];
        #pragma unroll
        for (int nt = 0; nt < 2; ++nt) {
            float s0  = acc[mt][nt][0] + bs;
            float s1  = acc[mt][nt][1] + bs;
            float tv0 = acc[mt][nt][2] + bt;
            float tv1 = acc[mt][nt][3] + bt;
            float g0 = __fdividef(1.f, 1.f + __expf(-s0)) *
                       (1.f - __fdividef(2.f, __expf(2.f * tv0) + 1.f));
            float g1 = __fdividef(1.f, 1.f + __expf(-s1)) *
                       (1.f - __fdividef(2.f, __expf(2.f * tv1) + 1.f));
            *(float2*)&d_g[(size_t)cg * BT + colbase + nt * 8] = make_float2(g0, g1);
        }
    }
}

// =====================================================================
// Skip/Res GEMM: M=768, K=512; RMW epilogue
// =====================================================================
__global__ __launch_bounds__(NTHREADS, 2)
void skipres_k(int l) {
    __shared__ float2 As2[BKK][LDA2];
    __shared__ float  Bs [BKK][LDB];

    int tid    = threadIdx.x;
    int lane   = tid & 31;
    int wid    = tid >> 5;
    int warp_m = wid & 1;
    int warp_n = wid >> 1;
    int mb     = blockIdx.x;        // 0..5
    int t0     = blockIdx.y * BN;
    int z      = blockIdx.z;

    const float*  gB = d_g + (size_t)z * TT;
    const float2* Al = d_Wrs2 + (size_t)l * NR * 768;

    float acc[4][2][4] = {};

    for (int kt = 0; kt < NR; kt += BKK) {
        #pragma unroll
        for (int p = 0; p < 8; ++p) {
            int e  = tid + p * 256;
            int k  = e >> 6;
            int m2 = (e & 63) << 1;
            *(float4*)&As2[k][m2] =
                *(const float4*)&Al[(size_t)(kt + k) * 768 + mb * 128 + m2];
        }
        #pragma unroll
        for (int p = 0; p < 2; ++p) {
            int e  = tid + p * 256;
            int k  = e >> 4;
            int n4 = (e & 15) << 2;
            *(float4*)&Bs[k][n4] =
                *(const float4*)&gB[(size_t)(kt + k) * BT + t0 + n4];
        }
        __syncthreads();
        MMA_COMPUTE3(acc, As2, Bs, warp_m, warp_n, lane);
        __syncthreads();
    }

    int colbase = z * TT + t0 + warp_n * 16 + (lane & 3) * 2;
    #pragma unroll
    for (int mt = 0; mt < 4; ++mt) {
        int r0 = warp_m * 64 + mt * 16 + (lane >> 2);
        #pragma unroll
        for (int half = 0; half < 2; ++half) {
            int mg = mb * 128 + r0 + half * 8;
            float bias = d_brs[l * 768 + mg];
            float* base = (mg < 256) ? &d_skip[(size_t)mg * BT]
                                     : &d_res[(size_t)(mg - 256) * BT];
            #pragma unroll
            for (int nt = 0; nt < 2; ++nt) {
                float* dst = base + colbase + nt * 8;
                float2 v = *(float2*)dst;
                v.x += acc[mt][nt][half * 2 + 0] + bias;
                v.y += acc[mt][nt][half * 2 + 1] + bias;
                *(float2*)dst = v;
            }
        }
    }
}

// =====================================================================
// Post GEMMs: M=256, N=8192, K=256
// =====================================================================
__global__ __launch_bounds__(NTHREADS, 2)
void post_k(int mode, const float* __restrict__ bias, float* __restrict__ outp) {
    __shared__ float2 As2[BKK][LDA2];
    __shared__ float  Bs [BKK][LDB];

    int tid    = threadIdx.x;
    int lane   = tid & 31;
    int wid    = tid >> 5;
    int warp_m = wid & 1;
    int warp_n = wid >> 1;
    int mb     = blockIdx.x;        // 0..1
    int j0     = blockIdx.y * BN;

    const float2* A    = (mode == 1) ? d_Wp12 : (mode == 2) ? d_Wp22 : d_Wp32;
    const float*  Bsrc = (mode == 2) ? d_g : d_skip;

    float acc[4][2][4] = {};

    for (int kt = 0; kt < 256; kt += BKK) {
        #pragma unroll
        for (int p = 0; p < 8; ++p) {
            int e  = tid + p * 256;
            int k  = e >> 6;
            int m2 = (e & 63) << 1;
            *(float4*)&As2[k][m2] =
                *(const float4*)&A[(size_t)(kt + k) * 256 + mb * 128 + m2];
        }
        #pragma unroll
        for (int p = 0; p < 2; ++p) {
            int e  = tid + p * 256;
            int k  = e >> 4;
            int n4 = (e & 15) << 2;
            float4 v = *(const float4*)&Bsrc[(size_t)(kt + k) * BT + j0 + n4];
            if (mode == 1) {
                v.x = fmaxf(v.x, 0.f); v.y = fmaxf(v.y, 0.f);
                v.z = fmaxf(v.z, 0.f); v.w = fmaxf(v.w, 0.f);
            }
            *(float4*)&Bs[k][n4] = v;
        }
        __syncthreads();
        MMA_COMPUTE3(acc, As2, Bs, warp_m, warp_n, lane);
        __syncthreads();
    }

    int colbase = j0 + warp_n * 16 + (lane & 3) * 2;
    #pragma unroll
    for (int mt = 0; mt < 4; ++mt) {
        int r0 = warp_m * 64 + mt * 16 + (lane >> 2);
        #pragma unroll
        for (int half = 0; half < 2; ++half) {
            int mg = mb * 128 + r0 + half * 8;
            float bv = bias[mg];
            #pragma unroll
            for (int nt = 0; nt < 2; ++nt) {
                float v0 = acc[mt][nt][half * 2 + 0] + bv;
                float v1 = acc[mt][nt][half * 2 + 1] + bv;
                if (mode == 1) { v0 = fmaxf(v0, 0.f); v1 = fmaxf(v1, 0.f); }
                int col = colbase + nt * 8;
                if (mode == 3) {
                    outp[(size_t)(col    ) * NQ + mg] = v0;
                    outp[(size_t)(col + 1) * NQ + mg] = v1;
                } else {
                    float* dst = (mode == 1) ? &d_g[(size_t)mg * BT + col]
                                             : &d_skip[(size_t)mg * BT + col];
                    *(float2*)dst = make_float2(v0, v1);
                }
            }
        }
    }
}

// =====================================================================
// Launch
// =====================================================================
extern "C" void kernel_launch(void* const* d_in, const int* in_sizes, int n_in,
                              void* d_out, int out_size) {
    const int*   x          = (const int*)  d_in[0];
    const float* h          = (const float*)d_in[1];
    const float* causal_w   = (const float*)d_in[2];
    const float* causal_b   = (const float*)d_in[3];
    const float* dil_sig_w  = (const float*)d_in[4];
    const float* dil_sig_b  = (const float*)d_in[5];
    const float* dil_tanh_w = (const float*)d_in[6];
    const float* dil_tanh_b = (const float*)d_in[7];
    const float* aux_sig_w  = (const float*)d_in[8];
    const float* aux_sig_b  = (const float*)d_in[9];
    const float* aux_tanh_w = (const float*)d_in[10];
    const float* aux_tanh_b = (const float*)d_in[11];
    const float* skip_w     = (const float*)d_in[12];
    const float* skip_b     = (const float*)d_in[13];
    const float* res_w      = (const float*)d_in[14];
    const float* res_b      = (const float*)d_in[15];
    const float* post1_w    = (const float*)d_in[16];
    const float* post1_b    = (const float*)d_in[17];
    const float* post2_w    = (const float*)d_in[18];
    const float* post2_b    = (const float*)d_in[19];
    const float* lin_w      = (const float*)d_in[20];
    const float* lin_b      = (const float*)d_in[21];

    { int n = NLAYERS * 2 * NR * 1024;        pack_gate_k<<<(n + 255) / 256, 256>>>(dil_sig_w, dil_tanh_w); }
    { int n = NLAYERS * NAUX * 1024;          pack_aux_k <<<(n + 255) / 256, 256>>>(aux_sig_w, aux_tanh_w); }
    { int n = NLAYERS * NR * 768;             pack_rs_k  <<<(n + 255) / 256, 256>>>(skip_w, res_w); }
    { int n = NLAYERS * 1024 + NLAYERS * 768; pack_bias_k<<<(n + 255) / 256, 256>>>(dil_sig_b, dil_tanh_b, aux_sig_b, aux_tanh_b, skip_b, res_b); }
    { int n = 3 * 65536;                      pack_post_k<<<(n + 255) / 256, 256>>>(post1_w, post2_w, lin_w); }

    zero_skip_k<<<(NS * BT + 255) / 256, 256>>>();
    embed_k<<<dim3(BT / 256, NR), 256>>>(x, causal_w, causal_b);

    for (int l = 0; l < NLAYERS; ++l) {
        int d = 1 << (l % 10);
        gate_k   <<<dim3(8, TT / BN, BATCH), NTHREADS>>>(l, d, h);
        skipres_k<<<dim3(6, TT / BN, BATCH), NTHREADS>>>(l);
    }

    post_k<<<dim3(2, BT / BN), NTHREADS>>>(1, post1_b, nullptr);
    post_k<<<dim3(2, BT / BN), NTHREADS>>>(2, post2_b, nullptr);
    post_k<<<dim3(2, BT / BN), NTHREADS>>>(3, lin_b, (float*)d_out);
}

// round 4
// speedup vs baseline: 2.1474x; 1.7487x over previous
#include <cuda_runtime.h>
#include <cuda_bf16.h>
#include <math.h>
#include <stdint.h>

// ---------------- problem constants ----------------
#define BATCH   2
#define TT      4096
#define BT      8192
#define NQ      256
#define NAUX    28
#define NR      512
#define NS      256
#define NLAYERS 30

// ---------------- GEMM tiling ----------------
#define BM 128
#define BN 64
#define BKK 32              // k per tile (16 k2-pairs)
#define NTHREADS 256
#define LDA 132             // A smem row stride in uint2 (== 4 mod 16 -> conflict-free LDS.64)
#define LDB 68              // B smem row stride in uint2

// ---------------- device scratch ----------------
__device__ float d_res [NR * BT];
__device__ float d_g   [NR * BT];
__device__ float d_skip[NS * BT];

// weights pre-split into packed bf16x2 (hi,lo) k-pair words:
// word for (k2, m): .x = {bf16 w[2k2], bf16 w[2k2+1]}  .y = same for lo residuals
__device__ uint2 d_Wg2 [NLAYERS * 2 * 256 * 1024];   // [l][tap][k2][m], gate-interleaved m
__device__ uint2 d_Wa2 [NLAYERS * 16 * 1024];        // aux padded to k2=16
__device__ uint2 d_Wrs2[NLAYERS * 256 * 768];
__device__ uint2 d_Wp12[128 * 256];
__device__ uint2 d_Wp22[128 * 256];
__device__ uint2 d_Wp32[128 * 256];
__device__ float d_bg  [NLAYERS * 1024];
__device__ float d_brs [NLAYERS * 768];

struct SmemTiles {
    uint2 A[2][16][LDA];
    uint2 B[2][16][LDB];
};
#define SMEM_BYTES ((int)sizeof(SmemTiles))   // 51200

// ---------------- helpers ----------------
__device__ __forceinline__ uint32_t pk2(__nv_bfloat16 a, __nv_bfloat16 b) {
    return (uint32_t)__bfloat16_as_ushort(a) | ((uint32_t)__bfloat16_as_ushort(b) << 16);
}

// split pair (x = k even elem, y = k odd elem) into (hi word, lo word)
__device__ __forceinline__ uint2 split2(float x, float y) {
    __nv_bfloat16 xh = __float2bfloat16_rn(x);
    __nv_bfloat16 yh = __float2bfloat16_rn(y);
    __nv_bfloat16 xl = __float2bfloat16_rn(x - __bfloat162float(xh));
    __nv_bfloat16 yl = __float2bfloat16_rn(y - __bfloat162float(yh));
    uint2 w;
    w.x = pk2(xh, yh);
    w.y = pk2(xl, yl);
    return w;
}

__device__ __forceinline__ void mma16(float* c, const uint32_t* a, const uint32_t* b) {
    asm volatile(
        "mma.sync.aligned.m16n8k16.row.col.f32.bf16.bf16.f32 "
        "{%0,%1,%2,%3}, {%4,%5,%6,%7}, {%8,%9}, {%0,%1,%2,%3};\n"
        : "+f"(c[0]), "+f"(c[1]), "+f"(c[2]), "+f"(c[3])
        : "r"(a[0]), "r"(a[1]), "r"(a[2]), "r"(a[3]), "r"(b[0]), "r"(b[1]));
}

// gate row interleave: channel cc (0..63) -> sig row 16*(cc/8)+cc%8, tanh +8
__device__ __forceinline__ int gate_channel_of_row(int mlocal) {
    return ((mlocal >> 4) << 3) | (mlocal & 7);
}

// 2-split bf16 3-MMA compute over one tile buffer pair
#define MMA3_TILE(acc, Ab, Bb, wm, wn, lane_)                                   \
    do {                                                                        \
        int c_ = (lane_) & 3, q_ = (lane_) >> 2;                                \
        _Pragma("unroll")                                                       \
        for (int ksb = 0; ksb < 2; ++ksb) {                                     \
            uint2 bw[2][2];                                                     \
            _Pragma("unroll")                                                   \
            for (int nt = 0; nt < 2; ++nt) {                                    \
                bw[nt][0] = (Bb)[ksb * 8 + c_][(wn) * 16 + nt * 8 + q_];        \
                bw[nt][1] = (Bb)[ksb * 8 + c_ + 4][(wn) * 16 + nt * 8 + q_];    \
            }                                                                   \
            _Pragma("unroll")                                                   \
            for (int mt = 0; mt < 4; ++mt) {                                    \
                int r_ = (wm) * 64 + mt * 16 + q_;                              \
                uint2 a0 = (Ab)[ksb * 8 + c_][r_];                              \
                uint2 a1 = (Ab)[ksb * 8 + c_][r_ + 8];                          \
                uint2 a2 = (Ab)[ksb * 8 + c_ + 4][r_];                          \
                uint2 a3 = (Ab)[ksb * 8 + c_ + 4][r_ + 8];                      \
                uint32_t ah_[4] = {a0.x, a1.x, a2.x, a3.x};                     \
                uint32_t al_[4] = {a0.y, a1.y, a2.y, a3.y};                     \
                _Pragma("unroll")                                               \
                for (int nt = 0; nt < 2; ++nt) {                                \
                    uint32_t bh_[2] = {bw[nt][0].x, bw[nt][1].x};               \
                    uint32_t bl_[2] = {bw[nt][0].y, bw[nt][1].y};               \
                    mma16(acc[mt][nt], ah_, bh_);                               \
                    mma16(acc[mt][nt], ah_, bl_);                               \
                    mma16(acc[mt][nt], al_, bh_);                               \
                }                                                               \
            }                                                                   \
        }                                                                       \
    } while (0)

// =====================================================================
// Packing kernels
// =====================================================================
__global__ void pack_gate_k(const float* __restrict__ ws, const float* __restrict__ wt) {
    int idx = blockIdx.x * blockDim.x + threadIdx.x;
    if (idx >= NLAYERS * 2 * 256 * 1024) return;
    int m   = idx & 1023;
    int r   = idx >> 10;
    int k2  = r & 255;
    int r2  = r >> 8;
    int tap = r2 & 1;
    int l   = r2 >> 1;
    int mlocal = m & 127;
    int half   = (mlocal >> 3) & 1;
    int cc     = gate_channel_of_row(mlocal & ~8);
    int c      = (m >> 7) * 64 + cc;
    const float* src = half ? wt : ws;
    size_t base = ((size_t)(l * NR + c) * NR + 2 * k2) * 2 + tap;
    d_Wg2[idx] = split2(src[base], src[base + 2]);
}

__global__ void pack_aux_k(const float* __restrict__ as_, const float* __restrict__ at_) {
    int idx = blockIdx.x * blockDim.x + threadIdx.x;
    if (idx >= NLAYERS * 16 * 1024) return;
    int m  = idx & 1023;
    int r  = idx >> 10;
    int k2 = r & 15;
    int l  = r >> 4;
    int mlocal = m & 127;
    int half   = (mlocal >> 3) & 1;
    int cc     = gate_channel_of_row(mlocal & ~8);
    int c      = (m >> 7) * 64 + cc;
    const float* src = half ? at_ : as_;
    int i0 = 2 * k2;
    float w0 = (i0 < NAUX)     ? src[(l * NR + c) * NAUX + i0]     : 0.f;
    float w1 = (i0 + 1 < NAUX) ? src[(l * NR + c) * NAUX + i0 + 1] : 0.f;
    d_Wa2[idx] = split2(w0, w1);
}

__global__ void pack_rs_k(const float* __restrict__ sw, const float* __restrict__ rw) {
    int idx = blockIdx.x * blockDim.x + threadIdx.x;
    if (idx >= NLAYERS * 256 * 768) return;
    int m  = idx % 768;
    int r  = idx / 768;
    int k2 = r & 255;
    int l  = r >> 8;
    int k0 = 2 * k2;
    float v0, v1;
    if (m < 256) {
        v0 = sw[(l * NS + m) * NR + k0];
        v1 = sw[(l * NS + m) * NR + k0 + 1];
    } else {
        v0 = rw[(l * NR + (m - 256)) * NR + k0];
        v1 = rw[(l * NR + (m - 256)) * NR + k0 + 1];
    }
    d_Wrs2[idx] = split2(v0, v1);
}

__global__ void pack_bias_k(const float* __restrict__ dsb, const float* __restrict__ dtb,
                            const float* __restrict__ asb, const float* __restrict__ atb,
                            const float* __restrict__ skb, const float* __restrict__ reb) {
    int idx = blockIdx.x * blockDim.x + threadIdx.x;
    if (idx < NLAYERS * 1024) {
        int l = idx >> 10;
        int m = idx & 1023;
        int mlocal = m & 127;
        int half   = (mlocal >> 3) & 1;
        int cc     = gate_channel_of_row(mlocal & ~8);
        int c      = (m >> 7) * 64 + cc;
        d_bg[idx] = half ? (dtb[l * NR + c] + atb[l * NR + c])
                         : (dsb[l * NR + c] + asb[l * NR + c]);
    } else if (idx < NLAYERS * 1024 + NLAYERS * 768) {
        int j = idx - NLAYERS * 1024;
        int l = j / 768;
        int m = j % 768;
        d_brs[j] = (m < 256) ? skb[l * NS + m] : reb[l * NR + (m - 256)];
    }
}

__global__ void pack_post_k(const float* __restrict__ p1, const float* __restrict__ p2,
                            const float* __restrict__ p3) {
    int idx = blockIdx.x * blockDim.x + threadIdx.x;
    if (idx >= 3 * 128 * 256) return;
    int w  = idx / 32768;
    int r  = idx % 32768;
    int k2 = r >> 8;
    int m  = r & 255;
    const float* p = (w == 0) ? p1 : (w == 1) ? p2 : p3;
    uint2 v = split2(p[m * 256 + 2 * k2], p[m * 256 + 2 * k2 + 1]);
    if (w == 0)      d_Wp12[r] = v;
    else if (w == 1) d_Wp22[r] = v;
    else             d_Wp32[r] = v;
}

__global__ void zero_skip_k() {
    int idx = blockIdx.x * blockDim.x + threadIdx.x;
    if (idx < NS * BT) d_skip[idx] = 0.f;
}

// =====================================================================
// Embedding (table lookup)
// =====================================================================
__global__ void embed_k(const int* __restrict__ x, const float* __restrict__ cw,
                        const float* __restrict__ cb) {
    int j = blockIdx.x * blockDim.x + threadIdx.x;
    int c = blockIdx.y;
    if (j >= BT) return;
    int b = j >> 12;
    int t = j & (TT - 1);
    int q1 = x[b * TT + t] & 255;
    float v = cw[(c * NQ + q1) * 2 + 1] + cb[c];
    if (t > 0) {
        int q0 = x[b * TT + t - 1] & 255;
        v += cw[(c * NQ + q0) * 2 + 0];
    }
    d_res[c * BT + j] = v;
}

// =====================================================================
// shared fetch / store-tile helpers
// =====================================================================
__device__ __forceinline__ void sts_tile(SmemTiles& S, int buf, int tid,
                                         const uint4* ra, float4 rb0, float4 rb1) {
    #pragma unroll
    for (int p = 0; p < 4; ++p) {
        int e  = tid + p * 256;
        int k2 = e >> 6;
        int m2 = (e & 63) << 1;
        *(uint4*)&S.A[buf][k2][m2] = ra[p];
    }
    int k2 = tid >> 4;
    int n4 = (tid & 15) << 2;
    const float* x0 = &rb0.x;
    const float* x1 = &rb1.x;
    #pragma unroll
    for (int j = 0; j < 4; ++j)
        S.B[buf][k2][n4 + j] = split2(x0[j], x1[j]);
}

// =====================================================================
// Gate GEMM: M=1024, N=4096/batch, K = 512(shifted) + 512 + 32(aux pad)
// 33 k-tiles, double-buffered, 1 sync/tile
// =====================================================================
__global__ __launch_bounds__(NTHREADS, 2)
void gate_k(int l, int d, const float* __restrict__ h) {
    extern __shared__ uint8_t smraw[];
    SmemTiles& S = *reinterpret_cast<SmemTiles*>(smraw);

    int tid    = threadIdx.x;
    int lane   = tid & 31;
    int wid    = tid >> 5;
    int warp_m = wid & 1;
    int warp_n = wid >> 1;
    int mb     = blockIdx.x;
    int t0     = blockIdx.y * BN;
    int z      = blockIdx.z;

    const float* resB = d_res + (size_t)z * TT;
    const float* hB   = h + (size_t)z * NAUX * TT;
    const uint2* A0 = d_Wg2 + (size_t)(l * 2 + 0) * 256 * 1024;
    const uint2* A1 = d_Wg2 + (size_t)(l * 2 + 1) * 256 * 1024;
    const uint2* A2 = d_Wa2 + (size_t)l * 16 * 1024;

    float acc[4][2][4] = {};
    uint4  ra[4];
    float4 rb0, rb1;

    // fetch tile -> registers
    auto FETCH = [&](int tile) {
        const uint2* Aseg; int kt2;
        if (tile < 16)      { Aseg = A0; kt2 = tile * 16; }
        else if (tile < 32) { Aseg = A1; kt2 = (tile - 16) * 16; }
        else                { Aseg = A2; kt2 = 0; }
        #pragma unroll
        for (int p = 0; p < 4; ++p) {
            int e  = tid + p * 256;
            int k2 = e >> 6;
            int m2 = (e & 63) << 1;
            ra[p] = *(const uint4*)&Aseg[(size_t)(kt2 + k2) * 1024 + mb * 128 + m2];
        }
        int k2 = tid >> 4;
        int n4 = (tid & 15) << 2;
        rb0 = make_float4(0.f, 0.f, 0.f, 0.f);
        rb1 = rb0;
        if (tile < 16) {
            int k0  = tile * 32 + 2 * k2;
            int col = t0 + n4 - d;
            if (((d & 3) == 0) && col >= 0) {
                rb0 = *(const float4*)&resB[(size_t)k0 * BT + col];
                rb1 = *(const float4*)&resB[(size_t)(k0 + 1) * BT + col];
            } else {
                float a0[4], a1[4];
                #pragma unroll
                for (int j = 0; j < 4; ++j) {
                    int cj = col + j;
                    a0[j] = (cj >= 0) ? resB[(size_t)k0 * BT + cj] : 0.f;
                    a1[j] = (cj >= 0) ? resB[(size_t)(k0 + 1) * BT + cj] : 0.f;
                }
                rb0 = make_float4(a0[0], a0[1], a0[2], a0[3]);
                rb1 = make_float4(a1[0], a1[1], a1[2], a1[3]);
            }
        } else if (tile < 32) {
            int k0 = (tile - 16) * 32 + 2 * k2;
            rb0 = *(const float4*)&resB[(size_t)k0 * BT + t0 + n4];
            rb1 = *(const float4*)&resB[(size_t)(k0 + 1) * BT + t0 + n4];
        } else {
            int k0 = 2 * k2;
            if (k0 < NAUX)     rb0 = *(const float4*)&hB[(size_t)k0 * TT + t0 + n4];
            if (k0 + 1 < NAUX) rb1 = *(const float4*)&hB[(size_t)(k0 + 1) * TT + t0 + n4];
        }
    };

    FETCH(0);
    sts_tile(S, 0, tid, ra, rb0, rb1);
    __syncthreads();

    const int NTILES = 33;
    for (int t = 0; t < NTILES; ++t) {
        if (t + 1 < NTILES) FETCH(t + 1);
        MMA3_TILE(acc, S.A[t & 1], S.B[t & 1], warp_m, warp_n, lane);
        if (t + 1 < NTILES) sts_tile(S, (t + 1) & 1, tid, ra, rb0, rb1);
        __syncthreads();
    }

    // gated activation epilogue
    const float* bgp = d_bg + l * 1024 + mb * 128;
    int colbase = z * TT + t0 + warp_n * 16 + (lane & 3) * 2;
    #pragma unroll
    for (int mt = 0; mt < 4; ++mt) {
        int r  = warp_m * 64 + mt * 16 + (lane >> 2);
        int cc = gate_channel_of_row(r);
        int cg = mb * 64 + cc;
        float bs = bgp[r];
        float bt = bgp[r + 8];
        #pragma unroll
        for (int nt = 0; nt < 2; ++nt) {
            float s0  = acc[mt][nt][0] + bs;
            float s1  = acc[mt][nt][1] + bs;
            float tv0 = acc[mt][nt][2] + bt;
            float tv1 = acc[mt][nt][3] + bt;
            float g0 = __fdividef(1.f, 1.f + __expf(-s0)) *
                       (1.f - __fdividef(2.f, __expf(2.f * tv0) + 1.f));
            float g1 = __fdividef(1.f, 1.f + __expf(-s1)) *
                       (1.f - __fdividef(2.f, __expf(2.f * tv1) + 1.f));
            *(float2*)&d_g[(size_t)cg * BT + colbase + nt * 8] = make_float2(g0, g1);
        }
    }
}

// =====================================================================
// Skip/Res GEMM: M=768, K=512 over g; RMW epilogue. 16 k-tiles.
// =====================================================================
__global__ __launch_bounds__(NTHREADS, 2)
void skipres_k(int l) {
    extern __shared__ uint8_t smraw[];
    SmemTiles& S = *reinterpret_cast<SmemTiles*>(smraw);

    int tid    = threadIdx.x;
    int lane   = tid & 31;
    int wid    = tid >> 5;
    int warp_m = wid & 1;
    int warp_n = wid >> 1;
    int mb     = blockIdx.x;
    int t0     = blockIdx.y * BN;
    int z      = blockIdx.z;

    const float* gB = d_g + (size_t)z * TT;
    const uint2* Al = d_Wrs2 + (size_t)l * 256 * 768;

    float acc[4][2][4] = {};
    uint4  ra[4];
    float4 rb0, rb1;

    auto FETCH = [&](int tile) {
        #pragma unroll
        for (int p = 0; p < 4; ++p) {
            int e  = tid + p * 256;
            int k2 = e >> 6;
            int m2 = (e & 63) << 1;
            ra[p] = *(const uint4*)&Al[(size_t)(tile * 16 + k2) * 768 + mb * 128 + m2];
        }
        int k2 = tid >> 4;
        int n4 = (tid & 15) << 2;
        int k0 = tile * 32 + 2 * k2;
        rb0 = *(const float4*)&gB[(size_t)k0 * BT + t0 + n4];
        rb1 = *(const float4*)&gB[(size_t)(k0 + 1) * BT + t0 + n4];
    };

    FETCH(0);
    sts_tile(S, 0, tid, ra, rb0, rb1);
    __syncthreads();

    const int NTILES = 16;
    for (int t = 0; t < NTILES; ++t) {
        if (t + 1 < NTILES) FETCH(t + 1);
        MMA3_TILE(acc, S.A[t & 1], S.B[t & 1], warp_m, warp_n, lane);
        if (t + 1 < NTILES) sts_tile(S, (t + 1) & 1, tid, ra, rb0, rb1);
        __syncthreads();
    }

    int colbase = z * TT + t0 + warp_n * 16 + (lane & 3) * 2;
    #pragma unroll
    for (int mt = 0; mt < 4; ++mt) {
        int r0 = warp_m * 64 + mt * 16 + (lane >> 2);
        #pragma unroll
        for (int half = 0; half < 2; ++half) {
            int mg = mb * 128 + r0 + half * 8;
            float bias = d_brs[l * 768 + mg];
            float* base = (mg < 256) ? &d_skip[(size_t)mg * BT]
                                     : &d_res[(size_t)(mg - 256) * BT];
            #pragma unroll
            for (int nt = 0; nt < 2; ++nt) {
                float* dst = base + colbase + nt * 8;
                float2 v = *(float2*)dst;
                v.x += acc[mt][nt][half * 2 + 0] + bias;
                v.y += acc[mt][nt][half * 2 + 1] + bias;
                *(float2*)dst = v;
            }
        }
    }
}

// =====================================================================
// Post GEMMs: M=256, N=8192, K=256. 8 k-tiles.
// =====================================================================
__global__ __launch_bounds__(NTHREADS, 2)
void post_k(int mode, const float* __restrict__ bias, float* __restrict__ outp) {
    extern __shared__ uint8_t smraw[];
    SmemTiles& S = *reinterpret_cast<SmemTiles*>(smraw);

    int tid    = threadIdx.x;
    int lane   = tid & 31;
    int wid    = tid >> 5;
    int warp_m = wid & 1;
    int warp_n = wid >> 1;
    int mb     = blockIdx.x;
    int j0     = blockIdx.y * BN;

    const uint2* A    = (mode == 1) ? d_Wp12 : (mode == 2) ? d_Wp22 : d_Wp32;
    const float* Bsrc = (mode == 2) ? d_g : d_skip;

    float acc[4][2][4] = {};
    uint4  ra[4];
    float4 rb0, rb1;

    auto FETCH = [&](int tile) {
        #pragma unroll
        for (int p = 0; p < 4; ++p) {
            int e  = tid + p * 256;
            int k2 = e >> 6;
            int m2 = (e & 63) << 1;
            ra[p] = *(const uint4*)&A[(size_t)(tile * 16 + k2) * 256 + mb * 128 + m2];
        }
        int k2 = tid >> 4;
        int n4 = (tid & 15) << 2;
        int k0 = tile * 32 + 2 * k2;
        rb0 = *(const float4*)&Bsrc[(size_t)k0 * BT + j0 + n4];
        rb1 = *(const float4*)&Bsrc[(size_t)(k0 + 1) * BT + j0 + n4];
        if (mode == 1) {
            rb0.x = fmaxf(rb0.x, 0.f); rb0.y = fmaxf(rb0.y, 0.f);
            rb0.z = fmaxf(rb0.z, 0.f); rb0.w = fmaxf(rb0.w, 0.f);
            rb1.x = fmaxf(rb1.x, 0.f); rb1.y = fmaxf(rb1.y, 0.f);
            rb1.z = fmaxf(rb1.z, 0.f); rb1.w = fmaxf(rb1.w, 0.f);
        }
    };

    FETCH(0);
    sts_tile(S, 0, tid, ra, rb0, rb1);
    __syncthreads();

    const int NTILES = 8;
    for (int t = 0; t < NTILES; ++t) {
        if (t + 1 < NTILES) FETCH(t + 1);
        MMA3_TILE(acc, S.A[t & 1], S.B[t & 1], warp_m, warp_n, lane);
        if (t + 1 < NTILES) sts_tile(S, (t + 1) & 1, tid, ra, rb0, rb1);
        __syncthreads();
    }

    int colbase = j0 + warp_n * 16 + (lane & 3) * 2;
    #pragma unroll
    for (int mt = 0; mt < 4; ++mt) {
        int r0 = warp_m * 64 + mt * 16 + (lane >> 2);
        #pragma unroll
        for (int half = 0; half < 2; ++half) {
            int mg = mb * 128 + r0 + half * 8;
            float bv = bias[mg];
            #pragma unroll
            for (int nt = 0; nt < 2; ++nt) {
                float v0 = acc[mt][nt][half * 2 + 0] + bv;
                float v1 = acc[mt][nt][half * 2 + 1] + bv;
                if (mode == 1) { v0 = fmaxf(v0, 0.f); v1 = fmaxf(v1, 0.f); }
                int col = colbase + nt * 8;
                if (mode == 3) {
                    outp[(size_t)(col    ) * NQ + mg] = v0;
                    outp[(size_t)(col + 1) * NQ + mg] = v1;
                } else {
                    float* dst = (mode == 1) ? &d_g[(size_t)mg * BT + col]
                                             : &d_skip[(size_t)mg * BT + col];
                    *(float2*)dst = make_float2(v0, v1);
                }
            }
        }
    }
}

// =====================================================================
// Launch
// =====================================================================
extern "C" void kernel_launch(void* const* d_in, const int* in_sizes, int n_in,
                              void* d_out, int out_size) {
    const int*   x          = (const int*)  d_in[0];
    const float* h          = (const float*)d_in[1];
    const float* causal_w   = (const float*)d_in[2];
    const float* causal_b   = (const float*)d_in[3];
    const float* dil_sig_w  = (const float*)d_in[4];
    const float* dil_sig_b  = (const float*)d_in[5];
    const float* dil_tanh_w = (const float*)d_in[6];
    const float* dil_tanh_b = (const float*)d_in[7];
    const float* aux_sig_w  = (const float*)d_in[8];
    const float* aux_sig_b  = (const float*)d_in[9];
    const float* aux_tanh_w = (const float*)d_in[10];
    const float* aux_tanh_b = (const float*)d_in[11];
    const float* skip_w     = (const float*)d_in[12];
    const float* skip_b     = (const float*)d_in[13];
    const float* res_w      = (const float*)d_in[14];
    const float* res_b      = (const float*)d_in[15];
    const float* post1_w    = (const float*)d_in[16];
    const float* post1_b    = (const float*)d_in[17];
    const float* post2_w    = (const float*)d_in[18];
    const float* post2_b    = (const float*)d_in[19];
    const float* lin_w      = (const float*)d_in[20];
    const float* lin_b      = (const float*)d_in[21];

    cudaFuncSetAttribute(gate_k,    cudaFuncAttributeMaxDynamicSharedMemorySize, SMEM_BYTES);
    cudaFuncSetAttribute(skipres_k, cudaFuncAttributeMaxDynamicSharedMemorySize, SMEM_BYTES);
    cudaFuncSetAttribute(post_k,    cudaFuncAttributeMaxDynamicSharedMemorySize, SMEM_BYTES);

    { int n = NLAYERS * 2 * 256 * 1024;       pack_gate_k<<<(n + 255) / 256, 256>>>(dil_sig_w, dil_tanh_w); }
    { int n = NLAYERS * 16 * 1024;            pack_aux_k <<<(n + 255) / 256, 256>>>(aux_sig_w, aux_tanh_w); }
    { int n = NLAYERS * 256 * 768;            pack_rs_k  <<<(n + 255) / 256, 256>>>(skip_w, res_w); }
    { int n = NLAYERS * 1024 + NLAYERS * 768; pack_bias_k<<<(n + 255) / 256, 256>>>(dil_sig_b, dil_tanh_b, aux_sig_b, aux_tanh_b, skip_b, res_b); }
    { int n = 3 * 128 * 256;                  pack_post_k<<<(n + 255) / 256, 256>>>(post1_w, post2_w, lin_w); }

    zero_skip_k<<<(NS * BT + 255) / 256, 256>>>();
    embed_k<<<dim3(BT / 256, NR), 256>>>(x, causal_w, causal_b);

    for (int l = 0; l < NLAYERS; ++l) {
        int d = 1 << (l % 10);
        gate_k   <<<dim3(8, TT / BN, BATCH), NTHREADS, SMEM_BYTES>>>(l, d, h);
        skipres_k<<<dim3(6, TT / BN, BATCH), NTHREADS, SMEM_BYTES>>>(l);
    }

    post_k<<<dim3(2, BT / BN), NTHREADS, SMEM_BYTES>>>(1, post1_b, nullptr);
    post_k<<<dim3(2, BT / BN), NTHREADS, SMEM_BYTES>>>(2, post2_b, nullptr);
    post_k<<<dim3(2, BT / BN), NTHREADS, SMEM_BYTES>>>(3, lin_b, (float*)d_out);
}

// round 5
// speedup vs baseline: 2.2817x; 1.0625x over previous
#include <cuda_runtime.h>
#include <cuda_bf16.h>
#include <math.h>
#include <stdint.h>

// ---------------- problem constants ----------------
#define BATCH   2
#define TT      4096
#define BT      8192
#define NQ      256
#define NAUX    28
#define NR      512
#define NS      256
#define NLAYERS 30

// ---------------- main GEMM tiling ----------------
#define BM 128
#define BN 128
#define NTHREADS 512
#define NSTAGES 4

// smem strides (elements)
#define SA 40        // A row: 32 k + 8 pad  (80B, conflict-free LDSM)
#define SB 136       // B row: 128 n + 8 pad (272B, conflict-free LDSM)

// ---------------- device scratch ----------------
__device__ float d_res [NR * BT];        // fp32 residual (exact accumulation)
__device__ float d_o1  [NS * BT];        // post scratch
__device__ float d_skip[NS * BT];

// activation bf16 hi/lo planes
__device__ __nv_bfloat16 d_resH[NR * BT], d_resL[NR * BT];
__device__ __nv_bfloat16 d_s1H [NR * BT], d_s1L [NR * BT];   // res shifted by 1 (d=1 layers)
__device__ __nv_bfloat16 d_gH  [NR * BT], d_gL  [NR * BT];
__device__ __nv_bfloat16 d_hH  [32 * BT], d_hL  [32 * BT];   // aux padded to 32 rows

// weight bf16 hi/lo planes, [m][k] row-major for ldmatrix(non-trans)
__device__ __nv_bfloat16 d_WgH [NLAYERS * 2 * 1024 * 512], d_WgL [NLAYERS * 2 * 1024 * 512];
__device__ __nv_bfloat16 d_WaH [NLAYERS * 1024 * 32],      d_WaL [NLAYERS * 1024 * 32];
__device__ __nv_bfloat16 d_WrsH[NLAYERS * 768 * 512],      d_WrsL[NLAYERS * 768 * 512];

__device__ float d_bg [NLAYERS * 1024];
__device__ float d_brs[NLAYERS * 768];

// post weights (register-split path, small)
__device__ uint2 d_Wp12[128 * 256];
__device__ uint2 d_Wp22[128 * 256];
__device__ uint2 d_Wp32[128 * 256];

// ---------------- helpers ----------------
__device__ __forceinline__ uint32_t pk2(__nv_bfloat16 a, __nv_bfloat16 b) {
    return (uint32_t)__bfloat16_as_ushort(a) | ((uint32_t)__bfloat16_as_ushort(b) << 16);
}

__device__ __forceinline__ uint2 split2(float x, float y) {
    __nv_bfloat16 xh = __float2bfloat16_rn(x);
    __nv_bfloat16 yh = __float2bfloat16_rn(y);
    __nv_bfloat16 xl = __float2bfloat16_rn(x - __bfloat162float(xh));
    __nv_bfloat16 yl = __float2bfloat16_rn(y - __bfloat162float(yh));
    uint2 w; w.x = pk2(xh, yh); w.y = pk2(xl, yl); return w;
}

__device__ __forceinline__ void mma16(float* c, const uint32_t* a, const uint32_t* b) {
    asm volatile(
        "mma.sync.aligned.m16n8k16.row.col.f32.bf16.bf16.f32 "
        "{%0,%1,%2,%3}, {%4,%5,%6,%7}, {%8,%9}, {%0,%1,%2,%3};\n"
        : "+f"(c[0]), "+f"(c[1]), "+f"(c[2]), "+f"(c[3])
        : "r"(a[0]), "r"(a[1]), "r"(a[2]), "r"(a[3]), "r"(b[0]), "r"(b[1]));
}

__device__ __forceinline__ void ldm_x4(uint32_t* r, uint32_t saddr) {
    asm volatile("ldmatrix.sync.aligned.m8n8.x4.shared.b16 {%0,%1,%2,%3}, [%4];"
        : "=r"(r[0]), "=r"(r[1]), "=r"(r[2]), "=r"(r[3]) : "r"(saddr));
}
__device__ __forceinline__ void ldm_x4t(uint32_t* r, uint32_t saddr) {
    asm volatile("ldmatrix.sync.aligned.m8n8.x4.trans.shared.b16 {%0,%1,%2,%3}, [%4];"
        : "=r"(r[0]), "=r"(r[1]), "=r"(r[2]), "=r"(r[3]) : "r"(saddr));
}

__device__ __forceinline__ void cp16(void* dst, const void* src) {
    uint32_t s = (uint32_t)__cvta_generic_to_shared(dst);
    asm volatile("cp.async.cg.shared.global [%0], [%1], 16;\n" :: "r"(s), "l"(src));
}
__device__ __forceinline__ void cp4z(void* dst, const void* src, int valid) {
    uint32_t s = (uint32_t)__cvta_generic_to_shared(dst);
    asm volatile("cp.async.ca.shared.global [%0], [%1], 4, %2;\n"
                 :: "r"(s), "l"(src), "r"(valid ? 4 : 0));
}
__device__ __forceinline__ void cp_commit() {
    asm volatile("cp.async.commit_group;\n" ::: "memory");
}
__device__ __forceinline__ void cp_wait2() {
    asm volatile("cp.async.wait_group 2;\n" ::: "memory");
}

// gate row interleave: channel cc (0..63) -> sig row 16*(cc/8)+cc%8, tanh +8
__device__ __forceinline__ int gate_channel_of_row(int mlocal) {
    return ((mlocal >> 4) << 3) | (mlocal & 7);
}

// smem stage
struct Stage {
    __nv_bfloat16 AH[128][SA];
    __nv_bfloat16 AL[128][SA];
    __nv_bfloat16 BH[32][SB];
    __nv_bfloat16 BL[32][SB];
};
static_assert(sizeof(Stage) == 37888, "stage size");
#define GEMM_SMEM (NSTAGES * (int)sizeof(Stage))     // 151552

// =====================================================================
// Packing kernels
// =====================================================================
__device__ __forceinline__ int gate_c_of_m(int m) {
    int mlocal = m & 127;
    int cc = gate_channel_of_row(mlocal & ~8);
    return (m >> 7) * 64 + cc;
}
__device__ __forceinline__ int gate_half_of_m(int m) { return (m >> 3) & 1; }

__global__ void pack_gate_k(const float* __restrict__ ws, const float* __restrict__ wt) {
    int idx = blockIdx.x * blockDim.x + threadIdx.x;
    if (idx >= NLAYERS * 2 * 1024 * 512) return;
    int k   = idx & 511;
    int rm  = idx >> 9;
    int m   = rm & 1023;
    int lt  = rm >> 10;
    int tap = lt & 1;
    int l   = lt >> 1;
    int c   = gate_c_of_m(m);
    const float* src = gate_half_of_m(m) ? wt : ws;
    float v = src[((size_t)(l * NR + c) * NR + k) * 2 + tap];
    __nv_bfloat16 hi = __float2bfloat16_rn(v);
    d_WgH[idx] = hi;
    d_WgL[idx] = __float2bfloat16_rn(v - __bfloat162float(hi));
}

__global__ void pack_aux_k(const float* __restrict__ as_, const float* __restrict__ at_) {
    int idx = blockIdx.x * blockDim.x + threadIdx.x;
    if (idx >= NLAYERS * 1024 * 32) return;
    int k  = idx & 31;
    int rm = idx >> 5;
    int m  = rm & 1023;
    int l  = rm >> 10;
    int c  = gate_c_of_m(m);
    const float* src = gate_half_of_m(m) ? at_ : as_;
    float v = (k < NAUX) ? src[(size_t)(l * NR + c) * NAUX + k] : 0.f;
    __nv_bfloat16 hi = __float2bfloat16_rn(v);
    d_WaH[idx] = hi;
    d_WaL[idx] = __float2bfloat16_rn(v - __bfloat162float(hi));
}

__global__ void pack_rs_k(const float* __restrict__ sw, const float* __restrict__ rw) {
    int idx = blockIdx.x * blockDim.x + threadIdx.x;
    if (idx >= NLAYERS * 768 * 512) return;
    int k  = idx & 511;
    int rm = idx >> 9;
    int m  = rm % 768;
    int l  = rm / 768;
    float v = (m < 256) ? sw[(size_t)(l * NS + m) * NR + k]
                        : rw[(size_t)(l * NR + (m - 256)) * NR + k];
    __nv_bfloat16 hi = __float2bfloat16_rn(v);
    d_WrsH[idx] = hi;
    d_WrsL[idx] = __float2bfloat16_rn(v - __bfloat162float(hi));
}

__global__ void pack_bias_k(const float* __restrict__ dsb, const float* __restrict__ dtb,
                            const float* __restrict__ asb, const float* __restrict__ atb,
                            const float* __restrict__ skb, const float* __restrict__ reb) {
    int idx = blockIdx.x * blockDim.x + threadIdx.x;
    if (idx < NLAYERS * 1024) {
        int l = idx >> 10;
        int m = idx & 1023;
        int c = gate_c_of_m(m);
        d_bg[idx] = gate_half_of_m(m) ? (dtb[l * NR + c] + atb[l * NR + c])
                                      : (dsb[l * NR + c] + asb[l * NR + c]);
    } else if (idx < NLAYERS * 1024 + NLAYERS * 768) {
        int j = idx - NLAYERS * 1024;
        int l = j / 768;
        int m = j % 768;
        d_brs[j] = (m < 256) ? skb[l * NS + m] : reb[l * NR + (m - 256)];
    }
}

__global__ void pack_post_k(const float* __restrict__ p1, const float* __restrict__ p2,
                            const float* __restrict__ p3) {
    int idx = blockIdx.x * blockDim.x + threadIdx.x;
    if (idx >= 3 * 128 * 256) return;
    int w  = idx / 32768;
    int r  = idx % 32768;
    int k2 = r >> 8;
    int m  = r & 255;
    const float* p = (w == 0) ? p1 : (w == 1) ? p2 : p3;
    uint2 v = split2(p[m * 256 + 2 * k2], p[m * 256 + 2 * k2 + 1]);
    if (w == 0)      d_Wp12[r] = v;
    else if (w == 1) d_Wp22[r] = v;
    else             d_Wp32[r] = v;
}

__global__ void zero_skip_k() {
    int idx = blockIdx.x * blockDim.x + threadIdx.x;
    if (idx < NS * BT) d_skip[idx] = 0.f;
}

__global__ void convert_h_k(const float* __restrict__ h) {
    int idx = blockIdx.x * blockDim.x + threadIdx.x;
    if (idx >= 32 * BT) return;
    int a = idx / BT, j = idx % BT;
    float v = 0.f;
    if (a < NAUX) {
        int b = j >> 12, t = j & (TT - 1);
        v = h[((size_t)b * NAUX + a) * TT + t];
    }
    __nv_bfloat16 hi = __float2bfloat16_rn(v);
    d_hH[idx] = hi;
    d_hL[idx] = __float2bfloat16_rn(v - __bfloat162float(hi));
}

__global__ void shift_k() {
    int idx = blockIdx.x * blockDim.x + threadIdx.x;
    if (idx >= NR * BT) return;
    int t = idx & (TT - 1);
    __nv_bfloat16 z = __float2bfloat16_rn(0.f);
    d_s1H[idx] = (t > 0) ? d_resH[idx - 1] : z;
    d_s1L[idx] = (t > 0) ? d_resL[idx - 1] : z;
}

// =====================================================================
// Embedding (table lookup) -> res fp32 + planes
// =====================================================================
__global__ void embed_k(const int* __restrict__ x, const float* __restrict__ cw,
                        const float* __restrict__ cb) {
    int j = blockIdx.x * blockDim.x + threadIdx.x;
    int c = blockIdx.y;
    if (j >= BT) return;
    int b = j >> 12;
    int t = j & (TT - 1);
    int q1 = x[b * TT + t] & 255;
    float v = cw[(c * NQ + q1) * 2 + 1] + cb[c];
    if (t > 0) {
        int q0 = x[b * TT + t - 1] & 255;
        v += cw[(c * NQ + q0) * 2 + 0];
    }
    d_res[c * BT + j] = v;
    __nv_bfloat16 hi = __float2bfloat16_rn(v);
    d_resH[c * BT + j] = hi;
    d_resL[c * BT + j] = __float2bfloat16_rn(v - __bfloat162float(hi));
}

// =====================================================================
// Gate GEMM: M=1024, N=8192, K = 512(shift d) + 512 + 32(aux)
// 33 k32-tiles, 4-stage cp.async pipeline, ldmatrix fragments.
// =====================================================================
__global__ __launch_bounds__(NTHREADS, 1)
void gate_k(int l, int d, int useS1) {
    extern __shared__ uint8_t smraw[];
    Stage* S = reinterpret_cast<Stage*>(smraw);

    int tid    = threadIdx.x;
    int lane   = tid & 31;
    int wid    = tid >> 5;          // 0..15
    int warp_m = wid & 1;
    int warp_n = wid >> 1;          // 0..7
    int mb     = blockIdx.x;        // 0..7
    int t0     = blockIdx.y * BN;   // 0..TT-128
    int z      = blockIdx.z;

    float acc[4][2][4] = {};

    // ldmatrix lane address components
    int subA  = lane >> 3;
    int rowA  = (subA & 1) * 8 + (lane & 7);
    int kbA   = (subA >> 1) * 16;                  // bytes
    int rowB  = lane & 15;
    int colBb = warp_n * 32 + (lane >> 4) * 16;    // bytes

    // ---- fill lambdas ----
    auto fillA = [&](int stage, int tile) {
        const __nv_bfloat16 *PH, *PL;
        int rowstride;
        if (tile < 32) {
            int tap = tile >> 4;
            int kt  = (tile & 15) * 32;
            size_t off = ((size_t)((l * 2 + tap) * 1024) + mb * 128) * 512 + kt;
            PH = d_WgH + off; PL = d_WgL + off; rowstride = 512;
        } else {
            size_t off = ((size_t)l * 1024 + mb * 128) * 32;
            PH = d_WaH + off; PL = d_WaL + off; rowstride = 32;
        }
        #pragma unroll
        for (int p = 0; p < 2; ++p) {
            int idx = tid + p * 512;
            int pl  = idx >> 9;
            int rem = idx & 511;
            int row = rem >> 2;
            int kc  = rem & 3;
            const __nv_bfloat16* src = (pl ? PL : PH) + (size_t)row * rowstride + kc * 8;
            __nv_bfloat16* dst = pl ? &S[stage].AL[row][kc * 8] : &S[stage].AH[row][kc * 8];
            cp16(dst, src);
        }
    };

    auto fillB = [&](int stage, int tile) {
        if (tile < 16) {
            // seg0: shifted res planes, 4B granularity
            const __nv_bfloat16* baseH = useS1 ? d_s1H : d_resH;
            const __nv_bfloat16* baseL = useS1 ? d_s1L : d_resL;
            int doff = useS1 ? 0 : d;
            int kt   = tile * 32;
            #pragma unroll
            for (int p = 0; p < 8; ++p) {
                int idx = tid + p * 512;
                int pl  = idx >> 11;
                int rem = idx & 2047;
                int row = rem >> 6;
                int c4  = rem & 63;
                int col = t0 + c4 * 2 - doff;
                const __nv_bfloat16* bp = pl ? baseL : baseH;
                const __nv_bfloat16* src = bp + (size_t)(kt + row) * BT + (size_t)z * TT
                                              + (col >= 0 ? col : 0);
                __nv_bfloat16* dst = pl ? &S[stage].BL[row][c4 * 2] : &S[stage].BH[row][c4 * 2];
                cp4z(dst, src, col >= 0);
            }
        } else {
            const __nv_bfloat16 *baseH, *baseL;
            int kt;
            if (tile < 32) { baseH = d_resH; baseL = d_resL; kt = (tile - 16) * 32; }
            else           { baseH = d_hH;   baseL = d_hL;   kt = 0; }
            #pragma unroll
            for (int p = 0; p < 2; ++p) {
                int idx = tid + p * 512;
                int pl  = idx >> 9;
                int rem = idx & 511;
                int row = rem >> 4;
                int c16 = rem & 15;
                const __nv_bfloat16* bp = pl ? baseL : baseH;
                const __nv_bfloat16* src = bp + (size_t)(kt + row) * BT + (size_t)z * TT
                                              + t0 + c16 * 8;
                __nv_bfloat16* dst = pl ? &S[stage].BL[row][c16 * 8] : &S[stage].BH[row][c16 * 8];
                cp16(dst, src);
            }
        }
    };

    auto compute = [&](int stage) {
        uint32_t aH = (uint32_t)__cvta_generic_to_shared(&S[stage].AH[0][0]);
        uint32_t aL = (uint32_t)__cvta_generic_to_shared(&S[stage].AL[0][0]);
        uint32_t bH = (uint32_t)__cvta_generic_to_shared(&S[stage].BH[0][0]);
        uint32_t bL = (uint32_t)__cvta_generic_to_shared(&S[stage].BL[0][0]);
        #pragma unroll
        for (int k16 = 0; k16 < 2; ++k16) {
            uint32_t afH[4][4], afL[4][4];
            #pragma unroll
            for (int mt = 0; mt < 4; ++mt) {
                uint32_t off = (uint32_t)((warp_m * 64 + mt * 16 + rowA) * (SA * 2)
                                          + k16 * 32 + kbA);
                ldm_x4(afH[mt], aH + off);
                ldm_x4(afL[mt], aL + off);
            }
            uint32_t bfH[4], bfL[4];
            uint32_t boff = (uint32_t)((k16 * 16 + rowB) * (SB * 2) + colBb);
            ldm_x4t(bfH, bH + boff);
            ldm_x4t(bfL, bL + boff);
            #pragma unroll
            for (int mt = 0; mt < 4; ++mt) {
                #pragma unroll
                for (int nt = 0; nt < 2; ++nt) {
                    mma16(acc[mt][nt], afH[mt], bfH + nt * 2);
                    mma16(acc[mt][nt], afH[mt], bfL + nt * 2);
                    mma16(acc[mt][nt], afL[mt], bfH + nt * 2);
                }
            }
        }
    };

    const int NT = 33;
    #pragma unroll
    for (int pt = 0; pt < 3; ++pt) { fillA(pt, pt); fillB(pt, pt); cp_commit(); }
    for (int t = 0; t < NT; ++t) {
        cp_wait2();
        __syncthreads();
        int nxt = t + 3;
        if (nxt < NT) { fillA(nxt & 3, nxt); fillB(nxt & 3, nxt); cp_commit(); }
        compute(t & 3);
    }

    // gated activation epilogue -> g planes
    const float* bgp = d_bg + l * 1024 + mb * 128;
    int colbase = z * TT + t0 + warp_n * 16 + (lane & 3) * 2;
    #pragma unroll
    for (int mt = 0; mt < 4; ++mt) {
        int r  = warp_m * 64 + mt * 16 + (lane >> 2);
        int cc = gate_channel_of_row(r);
        int cg = mb * 64 + cc;
        float bs = bgp[r];
        float bt = bgp[r + 8];
        #pragma unroll
        for (int nt = 0; nt < 2; ++nt) {
            float s0  = acc[mt][nt][0] + bs;
            float s1  = acc[mt][nt][1] + bs;
            float tv0 = acc[mt][nt][2] + bt;
            float tv1 = acc[mt][nt][3] + bt;
            float g0 = __fdividef(1.f, 1.f + __expf(-s0)) *
                       (1.f - __fdividef(2.f, __expf(2.f * tv0) + 1.f));
            float g1 = __fdividef(1.f, 1.f + __expf(-s1)) *
                       (1.f - __fdividef(2.f, __expf(2.f * tv1) + 1.f));
            uint2 w = split2(g0, g1);
            size_t o = (size_t)cg * BT + colbase + nt * 8;
            *(uint32_t*)&d_gH[o] = w.x;
            *(uint32_t*)&d_gL[o] = w.y;
        }
    }
}

// =====================================================================
// Skip/Res GEMM: M=768, K=512 over g planes; RMW fp32 + res planes
// =====================================================================
__global__ __launch_bounds__(NTHREADS, 1)
void skipres_k(int l) {
    extern __shared__ uint8_t smraw[];
    Stage* S = reinterpret_cast<Stage*>(smraw);

    int tid    = threadIdx.x;
    int lane   = tid & 31;
    int wid    = tid >> 5;
    int warp_m = wid & 1;
    int warp_n = wid >> 1;
    int mb     = blockIdx.x;        // 0..5
    int t0     = blockIdx.y * BN;
    int z      = blockIdx.z;

    float acc[4][2][4] = {};

    int subA  = lane >> 3;
    int rowA  = (subA & 1) * 8 + (lane & 7);
    int kbA   = (subA >> 1) * 16;
    int rowB  = lane & 15;
    int colBb = warp_n * 32 + (lane >> 4) * 16;

    size_t aoff = ((size_t)l * 768 + mb * 128) * 512;

    auto fillA = [&](int stage, int tile) {
        int kt = tile * 32;
        #pragma unroll
        for (int p = 0; p < 2; ++p) {
            int idx = tid + p * 512;
            int pl  = idx >> 9;
            int rem = idx & 511;
            int row = rem >> 2;
            int kc  = rem & 3;
            const __nv_bfloat16* src = (pl ? d_WrsL : d_WrsH) + aoff
                                        + (size_t)row * 512 + kt + kc * 8;
            __nv_bfloat16* dst = pl ? &S[stage].AL[row][kc * 8] : &S[stage].AH[row][kc * 8];
            cp16(dst, src);
        }
    };
    auto fillB = [&](int stage, int tile) {
        int kt = tile * 32;
        #pragma unroll
        for (int p = 0; p < 2; ++p) {
            int idx = tid + p * 512;
            int pl  = idx >> 9;
            int rem = idx & 511;
            int row = rem >> 4;
            int c16 = rem & 15;
            const __nv_bfloat16* bp = pl ? d_gL : d_gH;
            const __nv_bfloat16* src = bp + (size_t)(kt + row) * BT + (size_t)z * TT
                                          + t0 + c16 * 8;
            __nv_bfloat16* dst = pl ? &S[stage].BL[row][c16 * 8] : &S[stage].BH[row][c16 * 8];
            cp16(dst, src);
        }
    };
    auto compute = [&](int stage) {
        uint32_t aH = (uint32_t)__cvta_generic_to_shared(&S[stage].AH[0][0]);
        uint32_t aL = (uint32_t)__cvta_generic_to_shared(&S[stage].AL[0][0]);
        uint32_t bH = (uint32_t)__cvta_generic_to_shared(&S[stage].BH[0][0]);
        uint32_t bL = (uint32_t)__cvta_generic_to_shared(&S[stage].BL[0][0]);
        #pragma unroll
        for (int k16 = 0; k16 < 2; ++k16) {
            uint32_t afH[4][4], afL[4][4];
            #pragma unroll
            for (int mt = 0; mt < 4; ++mt) {
                uint32_t off = (uint32_t)((warp_m * 64 + mt * 16 + rowA) * (SA * 2)
                                          + k16 * 32 + kbA);
                ldm_x4(afH[mt], aH + off);
                ldm_x4(afL[mt], aL + off);
            }
            uint32_t bfH[4], bfL[4];
            uint32_t boff = (uint32_t)((k16 * 16 + rowB) * (SB * 2) + colBb);
            ldm_x4t(bfH, bH + boff);
            ldm_x4t(bfL, bL + boff);
            #pragma unroll
            for (int mt = 0; mt < 4; ++mt) {
                #pragma unroll
                for (int nt = 0; nt < 2; ++nt) {
                    mma16(acc[mt][nt], afH[mt], bfH + nt * 2);
                    mma16(acc[mt][nt], afH[mt], bfL + nt * 2);
                    mma16(acc[mt][nt], afL[mt], bfH + nt * 2);
                }
            }
        }
    };

    const int NT = 16;
    #pragma unroll
    for (int pt = 0; pt < 3; ++pt) { fillA(pt, pt); fillB(pt, pt); cp_commit(); }
    for (int t = 0; t < NT; ++t) {
        cp_wait2();
        __syncthreads();
        int nxt = t + 3;
        if (nxt < NT) { fillA(nxt & 3, nxt); fillB(nxt & 3, nxt); cp_commit(); }
        compute(t & 3);
    }

    int colbase = z * TT + t0 + warp_n * 16 + (lane & 3) * 2;
    #pragma unroll
    for (int mt = 0; mt < 4; ++mt) {
        int r0 = warp_m * 64 + mt * 16 + (lane >> 2);
        #pragma unroll
        for (int half = 0; half < 2; ++half) {
            int mg = mb * 128 + r0 + half * 8;
            float bias = d_brs[l * 768 + mg];
            #pragma unroll
            for (int nt = 0; nt < 2; ++nt) {
                int col = colbase + nt * 8;
                if (mg < 256) {
                    float* dst = &d_skip[(size_t)mg * BT + col];
                    float2 v = *(float2*)dst;
                    v.x += acc[mt][nt][half * 2 + 0] + bias;
                    v.y += acc[mt][nt][half * 2 + 1] + bias;
                    *(float2*)dst = v;
                } else {
                    int ch = mg - 256;
                    float* dst = &d_res[(size_t)ch * BT + col];
                    float2 v = *(float2*)dst;
                    v.x += acc[mt][nt][half * 2 + 0] + bias;
                    v.y += acc[mt][nt][half * 2 + 1] + bias;
                    *(float2*)dst = v;
                    uint2 w = split2(v.x, v.y);
                    size_t o = (size_t)ch * BT + col;
                    *(uint32_t*)&d_resH[o] = w.x;
                    *(uint32_t*)&d_resL[o] = w.y;
                }
            }
        }
    }
}

// =====================================================================
// Post GEMMs (register-split path, small): M=256, N=8192, K=256
// mode 1: d_o1   = relu(post1 @ relu(skip) + b)
// mode 2: d_skip = post2 @ d_o1 + b
// mode 3: out[j][q] = lin @ d_skip + lin_b (transposed store)
// =====================================================================
struct PostTiles {
    uint2 A[2][16][132];
    uint2 B[2][16][68];
};
#define POST_SMEM ((int)sizeof(PostTiles))   // 51200

__device__ __forceinline__ void post_sts(PostTiles& S, int buf, int tid,
                                         const uint4* ra, float4 rb0, float4 rb1) {
    #pragma unroll
    for (int p = 0; p < 4; ++p) {
        int e  = tid + p * 256;
        int k2 = e >> 6;
        int m2 = (e & 63) << 1;
        *(uint4*)&S.A[buf][k2][m2] = ra[p];
    }
    int k2 = tid >> 4;
    int n4 = (tid & 15) << 2;
    const float* x0 = &rb0.x;
    const float* x1 = &rb1.x;
    #pragma unroll
    for (int j = 0; j < 4; ++j)
        S.B[buf][k2][n4 + j] = split2(x0[j], x1[j]);
}

#define POST_MMA3(acc, Ab, Bb, wm, wn, lane_)                                   \
    do {                                                                        \
        int c_ = (lane_) & 3, q_ = (lane_) >> 2;                                \
        _Pragma("unroll")                                                       \
        for (int ksb = 0; ksb < 2; ++ksb) {                                     \
            uint2 bw[2][2];                                                     \
            _Pragma("unroll")                                                   \
            for (int nt = 0; nt < 2; ++nt) {                                    \
                bw[nt][0] = (Bb)[ksb * 8 + c_][(wn) * 16 + nt * 8 + q_];        \
                bw[nt][1] = (Bb)[ksb * 8 + c_ + 4][(wn) * 16 + nt * 8 + q_];    \
            }                                                                   \
            _Pragma("unroll")                                                   \
            for (int mt = 0; mt < 4; ++mt) {                                    \
                int r_ = (wm) * 64 + mt * 16 + q_;                              \
                uint2 a0 = (Ab)[ksb * 8 + c_][r_];                              \
                uint2 a1 = (Ab)[ksb * 8 + c_][r_ + 8];                          \
                uint2 a2 = (Ab)[ksb * 8 + c_ + 4][r_];                          \
                uint2 a3 = (Ab)[ksb * 8 + c_ + 4][r_ + 8];                      \
                uint32_t ah_[4] = {a0.x, a1.x, a2.x, a3.x};                     \
                uint32_t al_[4] = {a0.y, a1.y, a2.y, a3.y};                     \
                _Pragma("unroll")                                               \
                for (int nt = 0; nt < 2; ++nt) {                                \
                    uint32_t bh_[2] = {bw[nt][0].x, bw[nt][1].x};               \
                    uint32_t bl_[2] = {bw[nt][0].y, bw[nt][1].y};               \
                    mma16(acc[mt][nt], ah_, bh_);                               \
                    mma16(acc[mt][nt], ah_, bl_);                               \
                    mma16(acc[mt][nt], al_, bh_);                               \
                }                                                               \
            }                                                                   \
        }                                                                       \
    } while (0)

__global__ __launch_bounds__(256, 2)
void post_k(int mode, const float* __restrict__ bias, float* __restrict__ outp) {
    extern __shared__ uint8_t smraw[];
    PostTiles& S = *reinterpret_cast<PostTiles*>(smraw);

    int tid    = threadIdx.x;
    int lane   = tid & 31;
    int wid    = tid >> 5;
    int warp_m = wid & 1;
    int warp_n = wid >> 1;
    int mb     = blockIdx.x;
    int j0     = blockIdx.y * 64;

    const uint2* A    = (mode == 1) ? d_Wp12 : (mode == 2) ? d_Wp22 : d_Wp32;
    const float* Bsrc = (mode == 2) ? d_o1 : d_skip;

    float acc[4][2][4] = {};
    uint4  ra[4];
    float4 rb0, rb1;

    auto FETCH = [&](int tile) {
        #pragma unroll
        for (int p = 0; p < 4; ++p) {
            int e  = tid + p * 256;
            int k2 = e >> 6;
            int m2 = (e & 63) << 1;
            ra[p] = *(const uint4*)&A[(size_t)(tile * 16 + k2) * 256 + mb * 128 + m2];
        }
        int k2 = tid >> 4;
        int n4 = (tid & 15) << 2;
        int k0 = tile * 32 + 2 * k2;
        rb0 = *(const float4*)&Bsrc[(size_t)k0 * BT + j0 + n4];
        rb1 = *(const float4*)&Bsrc[(size_t)(k0 + 1) * BT + j0 + n4];
        if (mode == 1) {
            rb0.x = fmaxf(rb0.x, 0.f); rb0.y = fmaxf(rb0.y, 0.f);
            rb0.z = fmaxf(rb0.z, 0.f); rb0.w = fmaxf(rb0.w, 0.f);
            rb1.x = fmaxf(rb1.x, 0.f); rb1.y = fmaxf(rb1.y, 0.f);
            rb1.z = fmaxf(rb1.z, 0.f); rb1.w = fmaxf(rb1.w, 0.f);
        }
    };

    FETCH(0);
    post_sts(S, 0, tid, ra, rb0, rb1);
    __syncthreads();

    const int NT = 8;
    for (int t = 0; t < NT; ++t) {
        if (t + 1 < NT) FETCH(t + 1);
        POST_MMA3(acc, S.A[t & 1], S.B[t & 1], warp_m, warp_n, lane);
        if (t + 1 < NT) post_sts(S, (t + 1) & 1, tid, ra, rb0, rb1);
        __syncthreads();
    }

    int colbase = j0 + warp_n * 16 + (lane & 3) * 2;
    #pragma unroll
    for (int mt = 0; mt < 4; ++mt) {
        int r0 = warp_m * 64 + mt * 16 + (lane >> 2);
        #pragma unroll
        for (int half = 0; half < 2; ++half) {
            int mg = mb * 128 + r0 + half * 8;
            float bv = bias[mg];
            #pragma unroll
            for (int nt = 0; nt < 2; ++nt) {
                float v0 = acc[mt][nt][half * 2 + 0] + bv;
                float v1 = acc[mt][nt][half * 2 + 1] + bv;
                if (mode == 1) { v0 = fmaxf(v0, 0.f); v1 = fmaxf(v1, 0.f); }
                int col = colbase + nt * 8;
                if (mode == 3) {
                    outp[(size_t)(col    ) * NQ + mg] = v0;
                    outp[(size_t)(col + 1) * NQ + mg] = v1;
                } else {
                    float* dst = (mode == 1) ? &d_o1[(size_t)mg * BT + col]
                                             : &d_skip[(size_t)mg * BT + col];
                    *(float2*)dst = make_float2(v0, v1);
                }
            }
        }
    }
}

// =====================================================================
// Launch
// =====================================================================
extern "C" void kernel_launch(void* const* d_in, const int* in_sizes, int n_in,
                              void* d_out, int out_size) {
    const int*   x          = (const int*)  d_in[0];
    const float* h          = (const float*)d_in[1];
    const float* causal_w   = (const float*)d_in[2];
    const float* causal_b   = (const float*)d_in[3];
    const float* dil_sig_w  = (const float*)d_in[4];
    const float* dil_sig_b  = (const float*)d_in[5];
    const float* dil_tanh_w = (const float*)d_in[6];
    const float* dil_tanh_b = (const float*)d_in[7];
    const float* aux_sig_w  = (const float*)d_in[8];
    const float* aux_sig_b  = (const float*)d_in[9];
    const float* aux_tanh_w = (const float*)d_in[10];
    const float* aux_tanh_b = (const float*)d_in[11];
    const float* skip_w     = (const float*)d_in[12];
    const float* skip_b     = (const float*)d_in[13];
    const float* res_w      = (const float*)d_in[14];
    const float* res_b      = (const float*)d_in[15];
    const float* post1_w    = (const float*)d_in[16];
    const float* post1_b    = (const float*)d_in[17];
    const float* post2_w    = (const float*)d_in[18];
    const float* post2_b    = (const float*)d_in[19];
    const float* lin_w      = (const float*)d_in[20];
    const float* lin_b      = (const float*)d_in[21];

    cudaFuncSetAttribute(gate_k,    cudaFuncAttributeMaxDynamicSharedMemorySize, GEMM_SMEM);
    cudaFuncSetAttribute(skipres_k, cudaFuncAttributeMaxDynamicSharedMemorySize, GEMM_SMEM);
    cudaFuncSetAttribute(post_k,    cudaFuncAttributeMaxDynamicSharedMemorySize, POST_SMEM);

    { int n = NLAYERS * 2 * 1024 * 512;       pack_gate_k<<<(n + 255) / 256, 256>>>(dil_sig_w, dil_tanh_w); }
    { int n = NLAYERS * 1024 * 32;            pack_aux_k <<<(n + 255) / 256, 256>>>(aux_sig_w, aux_tanh_w); }
    { int n = NLAYERS * 768 * 512;            pack_rs_k  <<<(n + 255) / 256, 256>>>(skip_w, res_w); }
    { int n = NLAYERS * 1024 + NLAYERS * 768; pack_bias_k<<<(n + 255) / 256, 256>>>(dil_sig_b, dil_tanh_b, aux_sig_b, aux_tanh_b, skip_b, res_b); }
    { int n = 3 * 128 * 256;                  pack_post_k<<<(n + 255) / 256, 256>>>(post1_w, post2_w, lin_w); }

    zero_skip_k<<<(NS * BT + 255) / 256, 256>>>();
    convert_h_k<<<(32 * BT + 255) / 256, 256>>>(h);
    embed_k<<<dim3(BT / 256, NR), 256>>>(x, causal_w, causal_b);

    for (int l = 0; l < NLAYERS; ++l) {
        int d = 1 << (l % 10);
        int useS1 = (d == 1);
        if (useS1) shift_k<<<(NR * BT + 255) / 256, 256>>>();
        gate_k   <<<dim3(8, TT / BN, BATCH), NTHREADS, GEMM_SMEM>>>(l, d, useS1);
        skipres_k<<<dim3(6, TT / BN, BATCH), NTHREADS, GEMM_SMEM>>>(l);
    }

    post_k<<<dim3(2, BT / 64), 256, POST_SMEM>>>(1, post1_b, nullptr);
    post_k<<<dim3(2, BT / 64), 256, POST_SMEM>>>(2, post2_b, nullptr);
    post_k<<<dim3(2, BT / 64), 256, POST_SMEM>>>(3, lin_b, (float*)d_out);
}

// round 6
// speedup vs baseline: 2.7296x; 1.1963x over previous
#include <cuda_runtime.h>
#include <cuda_bf16.h>
#include <math.h>
#include <stdint.h>

// ---------------- problem constants ----------------
#define BATCH   2
#define TT      4096
#define BT      8192
#define NQ      256
#define NAUX    28
#define NR      512
#define NS      256
#define NLAYERS 30

// ---------------- main GEMM tiling ----------------
#define BM 128
#define BN 128
#define NTHREADS 256
#define NSTAGES 2

// smem strides (elements)
#define SA 40        // A row: 32 k + 8 pad  (80B, conflict-free LDSM)
#define SB 136       // B row: 128 n + 8 pad (272B, conflict-free LDSM)

// ---------------- device scratch ----------------
__device__ float d_res [NR * BT];        // fp32 residual (exact accumulation)
__device__ float d_o1  [NS * BT];
__device__ float d_skip[NS * BT];

// activation bf16 hi/lo planes
__device__ __nv_bfloat16 d_resH[NR * BT], d_resL[NR * BT];
__device__ __nv_bfloat16 d_s1H [NR * BT], d_s1L [NR * BT];   // res shifted by d (d<8 layers)
__device__ __nv_bfloat16 d_gH  [NR * BT], d_gL  [NR * BT];
__device__ __nv_bfloat16 d_hH  [32 * BT], d_hL  [32 * BT];

// weight bf16 hi/lo planes, [m][k] row-major
__device__ __nv_bfloat16 d_WgH [NLAYERS * 2 * 1024 * 512], d_WgL [NLAYERS * 2 * 1024 * 512];
__device__ __nv_bfloat16 d_WaH [NLAYERS * 1024 * 32],      d_WaL [NLAYERS * 1024 * 32];
__device__ __nv_bfloat16 d_WrsH[NLAYERS * 768 * 512],      d_WrsL[NLAYERS * 768 * 512];

__device__ float d_bg [NLAYERS * 1024];
__device__ float d_brs[NLAYERS * 768];

__device__ uint2 d_Wp12[128 * 256];
__device__ uint2 d_Wp22[128 * 256];
__device__ uint2 d_Wp32[128 * 256];

// ---------------- helpers ----------------
__device__ __forceinline__ uint32_t pk2(__nv_bfloat16 a, __nv_bfloat16 b) {
    return (uint32_t)__bfloat16_as_ushort(a) | ((uint32_t)__bfloat16_as_ushort(b) << 16);
}

__device__ __forceinline__ uint2 split2(float x, float y) {
    __nv_bfloat16 xh = __float2bfloat16_rn(x);
    __nv_bfloat16 yh = __float2bfloat16_rn(y);
    __nv_bfloat16 xl = __float2bfloat16_rn(x - __bfloat162float(xh));
    __nv_bfloat16 yl = __float2bfloat16_rn(y - __bfloat162float(yh));
    uint2 w; w.x = pk2(xh, yh); w.y = pk2(xl, yl); return w;
}

__device__ __forceinline__ void mma16(float* c, const uint32_t* a, const uint32_t* b) {
    asm volatile(
        "mma.sync.aligned.m16n8k16.row.col.f32.bf16.bf16.f32 "
        "{%0,%1,%2,%3}, {%4,%5,%6,%7}, {%8,%9}, {%0,%1,%2,%3};\n"
        : "+f"(c[0]), "+f"(c[1]), "+f"(c[2]), "+f"(c[3])
        : "r"(a[0]), "r"(a[1]), "r"(a[2]), "r"(a[3]), "r"(b[0]), "r"(b[1]));
}

__device__ __forceinline__ void ldm_x4(uint32_t* r, uint32_t saddr) {
    asm volatile("ldmatrix.sync.aligned.m8n8.x4.shared.b16 {%0,%1,%2,%3}, [%4];"
        : "=r"(r[0]), "=r"(r[1]), "=r"(r[2]), "=r"(r[3]) : "r"(saddr));
}
__device__ __forceinline__ void ldm_x4t(uint32_t* r, uint32_t saddr) {
    asm volatile("ldmatrix.sync.aligned.m8n8.x4.trans.shared.b16 {%0,%1,%2,%3}, [%4];"
        : "=r"(r[0]), "=r"(r[1]), "=r"(r[2]), "=r"(r[3]) : "r"(saddr));
}

__device__ __forceinline__ void cp16(void* dst, const void* src) {
    uint32_t s = (uint32_t)__cvta_generic_to_shared(dst);
    asm volatile("cp.async.cg.shared.global [%0], [%1], 16;\n" :: "r"(s), "l"(src));
}
__device__ __forceinline__ void cp16z(void* dst, const void* src, int valid) {
    uint32_t s = (uint32_t)__cvta_generic_to_shared(dst);
    asm volatile("cp.async.cg.shared.global [%0], [%1], 16, %2;\n"
                 :: "r"(s), "l"(src), "r"(valid ? 16 : 0));
}
__device__ __forceinline__ void cp_commit() {
    asm volatile("cp.async.commit_group;\n" ::: "memory");
}
__device__ __forceinline__ void cp_wait1() {
    asm volatile("cp.async.wait_group 1;\n" ::: "memory");
}
__device__ __forceinline__ void cp_wait0() {
    asm volatile("cp.async.wait_group 0;\n" ::: "memory");
}

__device__ __forceinline__ int gate_channel_of_row(int mlocal) {
    return ((mlocal >> 4) << 3) | (mlocal & 7);
}

struct Stage {
    __nv_bfloat16 AH[128][SA];
    __nv_bfloat16 AL[128][SA];
    __nv_bfloat16 BH[32][SB];
    __nv_bfloat16 BL[32][SB];
};
static_assert(sizeof(Stage) == 37888, "stage size");
#define GEMM_SMEM (NSTAGES * (int)sizeof(Stage))     // 75776

// =====================================================================
// Packing kernels
// =====================================================================
__device__ __forceinline__ int gate_c_of_m(int m) {
    int mlocal = m & 127;
    int cc = gate_channel_of_row(mlocal & ~8);
    return (m >> 7) * 64 + cc;
}
__device__ __forceinline__ int gate_half_of_m(int m) { return (m >> 3) & 1; }

__global__ void pack_gate_k(const float* __restrict__ ws, const float* __restrict__ wt) {
    int idx = blockIdx.x * blockDim.x + threadIdx.x;
    if (idx >= NLAYERS * 2 * 1024 * 512) return;
    int k   = idx & 511;
    int rm  = idx >> 9;
    int m   = rm & 1023;
    int lt  = rm >> 10;
    int tap = lt & 1;
    int l   = lt >> 1;
    int c   = gate_c_of_m(m);
    const float* src = gate_half_of_m(m) ? wt : ws;
    float v = src[((size_t)(l * NR + c) * NR + k) * 2 + tap];
    __nv_bfloat16 hi = __float2bfloat16_rn(v);
    d_WgH[idx] = hi;
    d_WgL[idx] = __float2bfloat16_rn(v - __bfloat162float(hi));
}

__global__ void pack_aux_k(const float* __restrict__ as_, const float* __restrict__ at_) {
    int idx = blockIdx.x * blockDim.x + threadIdx.x;
    if (idx >= NLAYERS * 1024 * 32) return;
    int k  = idx & 31;
    int rm = idx >> 5;
    int m  = rm & 1023;
    int l  = rm >> 10;
    int c  = gate_c_of_m(m);
    const float* src = gate_half_of_m(m) ? at_ : as_;
    float v = (k < NAUX) ? src[(size_t)(l * NR + c) * NAUX + k] : 0.f;
    __nv_bfloat16 hi = __float2bfloat16_rn(v);
    d_WaH[idx] = hi;
    d_WaL[idx] = __float2bfloat16_rn(v - __bfloat162float(hi));
}

__global__ void pack_rs_k(const float* __restrict__ sw, const float* __restrict__ rw) {
    int idx = blockIdx.x * blockDim.x + threadIdx.x;
    if (idx >= NLAYERS * 768 * 512) return;
    int k  = idx & 511;
    int rm = idx >> 9;
    int m  = rm % 768;
    int l  = rm / 768;
    float v = (m < 256) ? sw[(size_t)(l * NS + m) * NR + k]
                        : rw[(size_t)(l * NR + (m - 256)) * NR + k];
    __nv_bfloat16 hi = __float2bfloat16_rn(v);
    d_WrsH[idx] = hi;
    d_WrsL[idx] = __float2bfloat16_rn(v - __bfloat162float(hi));
}

__global__ void pack_bias_k(const float* __restrict__ dsb, const float* __restrict__ dtb,
                            const float* __restrict__ asb, const float* __restrict__ atb,
                            const float* __restrict__ skb, const float* __restrict__ reb) {
    int idx = blockIdx.x * blockDim.x + threadIdx.x;
    if (idx < NLAYERS * 1024) {
        int l = idx >> 10;
        int m = idx & 1023;
        int c = gate_c_of_m(m);
        d_bg[idx] = gate_half_of_m(m) ? (dtb[l * NR + c] + atb[l * NR + c])
                                      : (dsb[l * NR + c] + asb[l * NR + c]);
    } else if (idx < NLAYERS * 1024 + NLAYERS * 768) {
        int j = idx - NLAYERS * 1024;
        int l = j / 768;
        int m = j % 768;
        d_brs[j] = (m < 256) ? skb[l * NS + m] : reb[l * NR + (m - 256)];
    }
}

__global__ void pack_post_k(const float* __restrict__ p1, const float* __restrict__ p2,
                            const float* __restrict__ p3) {
    int idx = blockIdx.x * blockDim.x + threadIdx.x;
    if (idx >= 3 * 128 * 256) return;
    int w  = idx / 32768;
    int r  = idx % 32768;
    int k2 = r >> 8;
    int m  = r & 255;
    const float* p = (w == 0) ? p1 : (w == 1) ? p2 : p3;
    uint2 v = split2(p[m * 256 + 2 * k2], p[m * 256 + 2 * k2 + 1]);
    if (w == 0)      d_Wp12[r] = v;
    else if (w == 1) d_Wp22[r] = v;
    else             d_Wp32[r] = v;
}

__global__ void zero_skip_k() {
    int idx = blockIdx.x * blockDim.x + threadIdx.x;
    if (idx < NS * BT) d_skip[idx] = 0.f;
}

__global__ void convert_h_k(const float* __restrict__ h) {
    int idx = blockIdx.x * blockDim.x + threadIdx.x;
    if (idx >= 32 * BT) return;
    int a = idx / BT, j = idx % BT;
    float v = 0.f;
    if (a < NAUX) {
        int b = j >> 12, t = j & (TT - 1);
        v = h[((size_t)b * NAUX + a) * TT + t];
    }
    __nv_bfloat16 hi = __float2bfloat16_rn(v);
    d_hH[idx] = hi;
    d_hL[idx] = __float2bfloat16_rn(v - __bfloat162float(hi));
}

// shift res planes by d within each batch row (d in {1,2,4})
__global__ void shift_k(int d) {
    int idx = blockIdx.x * blockDim.x + threadIdx.x;
    if (idx >= NR * BT) return;
    int t = idx & (TT - 1);
    __nv_bfloat16 z = __float2bfloat16_rn(0.f);
    d_s1H[idx] = (t >= d) ? d_resH[idx - d] : z;
    d_s1L[idx] = (t >= d) ? d_resL[idx - d] : z;
}

// =====================================================================
// Embedding (table lookup) -> res fp32 + planes
// =====================================================================
__global__ void embed_k(const int* __restrict__ x, const float* __restrict__ cw,
                        const float* __restrict__ cb) {
    int j = blockIdx.x * blockDim.x + threadIdx.x;
    int c = blockIdx.y;
    if (j >= BT) return;
    int b = j >> 12;
    int t = j & (TT - 1);
    int q1 = x[b * TT + t] & 255;
    float v = cw[(c * NQ + q1) * 2 + 1] + cb[c];
    if (t > 0) {
        int q0 = x[b * TT + t - 1] & 255;
        v += cw[(c * NQ + q0) * 2 + 0];
    }
    d_res[c * BT + j] = v;
    __nv_bfloat16 hi = __float2bfloat16_rn(v);
    d_resH[c * BT + j] = hi;
    d_resL[c * BT + j] = __float2bfloat16_rn(v - __bfloat162float(hi));
}

// =====================================================================
// Gate GEMM: M=1024, N=8192, K = 512(shift d) + 512 + 32(aux)
// 33 k32-tiles, 2-stage cp.async pipeline, occupancy 2.
// =====================================================================
__global__ __launch_bounds__(NTHREADS, 2)
void gate_k(int l, int d, int useS1) {
    extern __shared__ uint8_t smraw[];
    Stage* S = reinterpret_cast<Stage*>(smraw);

    int tid    = threadIdx.x;
    int lane   = tid & 31;
    int wid    = tid >> 5;          // 0..7
    int warp_m = wid & 1;
    int warp_n = wid >> 1;          // 0..3 (n32 each)
    int mb     = blockIdx.x;        // 0..7
    int t0     = blockIdx.y * BN;
    int z      = blockIdx.z;

    float acc[4][4][4] = {};

    int subA  = lane >> 3;
    int rowA  = (subA & 1) * 8 + (lane & 7);
    int kbA   = (subA >> 1) * 16;
    int rowB  = lane & 15;
    int colBq = (lane >> 4) * 16;   // bytes within n16 group

    auto fillA = [&](int stage, int tile) {
        const __nv_bfloat16 *PH, *PL;
        int rowstride;
        if (tile < 32) {
            int tap = tile >> 4;
            int kt  = (tile & 15) * 32;
            size_t off = ((size_t)((l * 2 + tap) * 1024) + mb * 128) * 512 + kt;
            PH = d_WgH + off; PL = d_WgL + off; rowstride = 512;
        } else {
            size_t off = ((size_t)l * 1024 + mb * 128) * 32;
            PH = d_WaH + off; PL = d_WaL + off; rowstride = 32;
        }
        #pragma unroll
        for (int p = 0; p < 4; ++p) {
            int idx = tid + p * 256;
            int pl  = idx >> 9;
            int rem = idx & 511;
            int row = rem >> 2;
            int kc  = rem & 3;
            const __nv_bfloat16* src = (pl ? PL : PH) + (size_t)row * rowstride + kc * 8;
            __nv_bfloat16* dst = pl ? &S[stage].AL[row][kc * 8] : &S[stage].AH[row][kc * 8];
            cp16(dst, src);
        }
    };

    auto fillB = [&](int stage, int tile) {
        const __nv_bfloat16 *baseH, *baseL;
        int kt, doff;
        if (tile < 16) {
            baseH = useS1 ? d_s1H : d_resH;
            baseL = useS1 ? d_s1L : d_resL;
            kt = tile * 32; doff = useS1 ? 0 : d;
        } else if (tile < 32) {
            baseH = d_resH; baseL = d_resL; kt = (tile - 16) * 32; doff = 0;
        } else {
            baseH = d_hH; baseL = d_hL; kt = 0; doff = 0;
        }
        #pragma unroll
        for (int p = 0; p < 4; ++p) {
            int idx = tid + p * 256;
            int pl  = idx >> 9;
            int rem = idx & 511;
            int row = rem >> 4;
            int c16 = rem & 15;
            int col = t0 + c16 * 8 - doff;      // doff multiple of 8 -> chunk all-or-none
            const __nv_bfloat16* bp = pl ? baseL : baseH;
            const __nv_bfloat16* src = bp + (size_t)(kt + row) * BT + (size_t)z * TT
                                          + (col >= 0 ? col : 0);
            __nv_bfloat16* dst = pl ? &S[stage].BL[row][c16 * 8] : &S[stage].BH[row][c16 * 8];
            cp16z(dst, src, col >= 0);
        }
    };

    auto compute = [&](int stage) {
        uint32_t aH = (uint32_t)__cvta_generic_to_shared(&S[stage].AH[0][0]);
        uint32_t aL = (uint32_t)__cvta_generic_to_shared(&S[stage].AL[0][0]);
        uint32_t bH = (uint32_t)__cvta_generic_to_shared(&S[stage].BH[0][0]);
        uint32_t bL = (uint32_t)__cvta_generic_to_shared(&S[stage].BL[0][0]);
        #pragma unroll
        for (int k16 = 0; k16 < 2; ++k16) {
            uint32_t bfH[2][4], bfL[2][4];
            #pragma unroll
            for (int hh = 0; hh < 2; ++hh) {
                uint32_t boff = (uint32_t)((k16 * 16 + rowB) * (SB * 2)
                                           + warp_n * 64 + hh * 32 + colBq);
                ldm_x4t(bfH[hh], bH + boff);
                ldm_x4t(bfL[hh], bL + boff);
            }
            #pragma unroll
            for (int mt = 0; mt < 4; ++mt) {
                uint32_t afH[4], afL[4];
                uint32_t off = (uint32_t)((warp_m * 64 + mt * 16 + rowA) * (SA * 2)
                                          + k16 * 32 + kbA);
                ldm_x4(afH, aH + off);
                ldm_x4(afL, aL + off);
                #pragma unroll
                for (int nt = 0; nt < 4; ++nt) {
                    int hh = nt >> 1, ss = (nt & 1) * 2;
                    mma16(acc[mt][nt], afH, bfH[hh] + ss);
                    mma16(acc[mt][nt], afH, bfL[hh] + ss);
                    mma16(acc[mt][nt], afL, bfH[hh] + ss);
                }
            }
        }
    };

    const int NT = 33;
    fillA(0, 0); fillB(0, 0); cp_commit();
    fillA(1, 1); fillB(1, 1); cp_commit();
    for (int t = 0; t < NT; ++t) {
        if (t + 1 < NT) cp_wait1(); else cp_wait0();
        __syncthreads();
        compute(t & 1);
        __syncthreads();
        if (t + 2 < NT) { fillA(t & 1, t + 2); fillB(t & 1, t + 2); cp_commit(); }
    }

    // gated activation epilogue -> g planes
    const float* bgp = d_bg + l * 1024 + mb * 128;
    int colbase = z * TT + t0 + warp_n * 32 + (lane & 3) * 2;
    #pragma unroll
    for (int mt = 0; mt < 4; ++mt) {
        int r  = warp_m * 64 + mt * 16 + (lane >> 2);
        int cc = gate_channel_of_row(r);
        int cg = mb * 64 + cc;
        float bs = bgp[r];
        float bt = bgp[r + 8];
        #pragma unroll
        for (int nt = 0; nt < 4; ++nt) {
            float s0  = acc[mt][nt][0] + bs;
            float s1  = acc[mt][nt][1] + bs;
            float tv0 = acc[mt][nt][2] + bt;
            float tv1 = acc[mt][nt][3] + bt;
            float g0 = __fdividef(1.f, 1.f + __expf(-s0)) *
                       (1.f - __fdividef(2.f, __expf(2.f * tv0) + 1.f));
            float g1 = __fdividef(1.f, 1.f + __expf(-s1)) *
                       (1.f - __fdividef(2.f, __expf(2.f * tv1) + 1.f));
            uint2 w = split2(g0, g1);
            size_t o = (size_t)cg * BT + colbase + nt * 8;
            *(uint32_t*)&d_gH[o] = w.x;
            *(uint32_t*)&d_gL[o] = w.y;
        }
    }
}

// =====================================================================
// Skip/Res GEMM: M=768, K=512 over g planes; RMW fp32 + res planes
// =====================================================================
__global__ __launch_bounds__(NTHREADS, 2)
void skipres_k(int l) {
    extern __shared__ uint8_t smraw[];
    Stage* S = reinterpret_cast<Stage*>(smraw);

    int tid    = threadIdx.x;
    int lane   = tid & 31;
    int wid    = tid >> 5;
    int warp_m = wid & 1;
    int warp_n = wid >> 1;
    int mb     = blockIdx.x;        // 0..5
    int t0     = blockIdx.y * BN;
    int z      = blockIdx.z;

    float acc[4][4][4] = {};

    int subA  = lane >> 3;
    int rowA  = (subA & 1) * 8 + (lane & 7);
    int kbA   = (subA >> 1) * 16;
    int rowB  = lane & 15;
    int colBq = (lane >> 4) * 16;

    size_t aoff = ((size_t)l * 768 + mb * 128) * 512;

    auto fillA = [&](int stage, int tile) {
        int kt = tile * 32;
        #pragma unroll
        for (int p = 0; p < 4; ++p) {
            int idx = tid + p * 256;
            int pl  = idx >> 9;
            int rem = idx & 511;
            int row = rem >> 2;
            int kc  = rem & 3;
            const __nv_bfloat16* src = (pl ? d_WrsL : d_WrsH) + aoff
                                        + (size_t)row * 512 + kt + kc * 8;
            __nv_bfloat16* dst = pl ? &S[stage].AL[row][kc * 8] : &S[stage].AH[row][kc * 8];
            cp16(dst, src);
        }
    };
    auto fillB = [&](int stage, int tile) {
        int kt = tile * 32;
        #pragma unroll
        for (int p = 0; p < 4; ++p) {
            int idx = tid + p * 256;
            int pl  = idx >> 9;
            int rem = idx & 511;
            int row = rem >> 4;
            int c16 = rem & 15;
            const __nv_bfloat16* bp = pl ? d_gL : d_gH;
            const __nv_bfloat16* src = bp + (size_t)(kt + row) * BT + (size_t)z * TT
                                          + t0 + c16 * 8;
            __nv_bfloat16* dst = pl ? &S[stage].BL[row][c16 * 8] : &S[stage].BH[row][c16 * 8];
            cp16(dst, src);
        }
    };
    auto compute = [&](int stage) {
        uint32_t aH = (uint32_t)__cvta_generic_to_shared(&S[stage].AH[0][0]);
        uint32_t aL = (uint32_t)__cvta_generic_to_shared(&S[stage].AL[0][0]);
        uint32_t bH = (uint32_t)__cvta_generic_to_shared(&S[stage].BH[0][0]);
        uint32_t bL = (uint32_t)__cvta_generic_to_shared(&S[stage].BL[0][0]);
        #pragma unroll
        for (int k16 = 0; k16 < 2; ++k16) {
            uint32_t bfH[2][4], bfL[2][4];
            #pragma unroll
            for (int hh = 0; hh < 2; ++hh) {
                uint32_t boff = (uint32_t)((k16 * 16 + rowB) * (SB * 2)
                                           + warp_n * 64 + hh * 32 + colBq);
                ldm_x4t(bfH[hh], bH + boff);
                ldm_x4t(bfL[hh], bL + boff);
            }
            #pragma unroll
            for (int mt = 0; mt < 4; ++mt) {
                uint32_t afH[4], afL[4];
                uint32_t off = (uint32_t)((warp_m * 64 + mt * 16 + rowA) * (SA * 2)
                                          + k16 * 32 + kbA);
                ldm_x4(afH, aH + off);
                ldm_x4(afL, aL + off);
                #pragma unroll
                for (int nt = 0; nt < 4; ++nt) {
                    int hh = nt >> 1, ss = (nt & 1) * 2;
                    mma16(acc[mt][nt], afH, bfH[hh] + ss);
                    mma16(acc[mt][nt], afH, bfL[hh] + ss);
                    mma16(acc[mt][nt], afL, bfH[hh] + ss);
                }
            }
        }
    };

    const int NT = 16;
    fillA(0, 0); fillB(0, 0); cp_commit();
    fillA(1, 1); fillB(1, 1); cp_commit();
    for (int t = 0; t < NT; ++t) {
        if (t + 1 < NT) cp_wait1(); else cp_wait0();
        __syncthreads();
        compute(t & 1);
        __syncthreads();
        if (t + 2 < NT) { fillA(t & 1, t + 2); fillB(t & 1, t + 2); cp_commit(); }
    }

    int colbase = z * TT + t0 + warp_n * 32 + (lane & 3) * 2;
    #pragma unroll
    for (int mt = 0; mt < 4; ++mt) {
        int r0 = warp_m * 64 + mt * 16 + (lane >> 2);
        #pragma unroll
        for (int half = 0; half < 2; ++half) {
            int mg = mb * 128 + r0 + half * 8;
            float bias = d_brs[l * 768 + mg];
            #pragma unroll
            for (int nt = 0; nt < 4; ++nt) {
                int col = colbase + nt * 8;
                if (mg < 256) {
                    float* dst = &d_skip[(size_t)mg * BT + col];
                    float2 v = *(float2*)dst;
                    v.x += acc[mt][nt][half * 2 + 0] + bias;
                    v.y += acc[mt][nt][half * 2 + 1] + bias;
                    *(float2*)dst = v;
                } else {
                    int ch = mg - 256;
                    float* dst = &d_res[(size_t)ch * BT + col];
                    float2 v = *(float2*)dst;
                    v.x += acc[mt][nt][half * 2 + 0] + bias;
                    v.y += acc[mt][nt][half * 2 + 1] + bias;
                    *(float2*)dst = v;
                    uint2 w = split2(v.x, v.y);
                    size_t o = (size_t)ch * BT + col;
                    *(uint32_t*)&d_resH[o] = w.x;
                    *(uint32_t*)&d_resL[o] = w.y;
                }
            }
        }
    }
}

// =====================================================================
// Post GEMMs (register-split path): M=256, N=8192, K=256
// =====================================================================
struct PostTiles {
    uint2 A[2][16][132];
    uint2 B[2][16][68];
};
#define POST_SMEM ((int)sizeof(PostTiles))

__device__ __forceinline__ void post_sts(PostTiles& S, int buf, int tid,
                                         const uint4* ra, float4 rb0, float4 rb1) {
    #pragma unroll
    for (int p = 0; p < 4; ++p) {
        int e  = tid + p * 256;
        int k2 = e >> 6;
        int m2 = (e & 63) << 1;
        *(uint4*)&S.A[buf][k2][m2] = ra[p];
    }
    int k2 = tid >> 4;
    int n4 = (tid & 15) << 2;
    const float* x0 = &rb0.x;
    const float* x1 = &rb1.x;
    #pragma unroll
    for (int j = 0; j < 4; ++j)
        S.B[buf][k2][n4 + j] = split2(x0[j], x1[j]);
}

#define POST_MMA3(acc, Ab, Bb, wm, wn, lane_)                                   \
    do {                                                                        \
        int c_ = (lane_) & 3, q_ = (lane_) >> 2;                                \
        _Pragma("unroll")                                                       \
        for (int ksb = 0; ksb < 2; ++ksb) {                                     \
            uint2 bw[2][2];                                                     \
            _Pragma("unroll")                                                   \
            for (int nt = 0; nt < 2; ++nt) {                                    \
                bw[nt][0] = (Bb)[ksb * 8 + c_][(wn) * 16 + nt * 8 + q_];        \
                bw[nt][1] = (Bb)[ksb * 8 + c_ + 4][(wn) * 16 + nt * 8 + q_];    \
            }                                                                   \
            _Pragma("unroll")                                                   \
            for (int mt = 0; mt < 4; ++mt) {                                    \
                int r_ = (wm) * 64 + mt * 16 + q_;                              \
                uint2 a0 = (Ab)[ksb * 8 + c_][r_];                              \
                uint2 a1 = (Ab)[ksb * 8 + c_][r_ + 8];                          \
                uint2 a2 = (Ab)[ksb * 8 + c_ + 4][r_];                          \
                uint2 a3 = (Ab)[ksb * 8 + c_ + 4][r_ + 8];                      \
                uint32_t ah_[4] = {a0.x, a1.x, a2.x, a3.x};                     \
                uint32_t al_[4] = {a0.y, a1.y, a2.y, a3.y};                     \
                _Pragma("unroll")                                               \
                for (int nt = 0; nt < 2; ++nt) {                                \
                    uint32_t bh_[2] = {bw[nt][0].x, bw[nt][1].x};               \
                    uint32_t bl_[2] = {bw[nt][0].y, bw[nt][1].y};               \
                    mma16(acc[mt][nt], ah_, bh_);                               \
                    mma16(acc[mt][nt], ah_, bl_);                               \
                    mma16(acc[mt][nt], al_, bh_);                               \
                }                                                               \
            }                                                                   \
        }                                                                       \
    } while (0)

__global__ __launch_bounds__(256, 2)
void post_k(int mode, const float* __restrict__ bias, float* __restrict__ outp) {
    extern __shared__ uint8_t smraw[];
    PostTiles& S = *reinterpret_cast<PostTiles*>(smraw);

    int tid    = threadIdx.x;
    int lane   = tid & 31;
    int wid    = tid >> 5;
    int warp_m = wid & 1;
    int warp_n = wid >> 1;
    int mb     = blockIdx.x;
    int j0     = blockIdx.y * 64;

    const uint2* A    = (mode == 1) ? d_Wp12 : (mode == 2) ? d_Wp22 : d_Wp32;
    const float* Bsrc = (mode == 2) ? d_o1 : d_skip;

    float acc[4][2][4] = {};
    uint4  ra[4];
    float4 rb0, rb1;

    auto FETCH = [&](int tile) {
        #pragma unroll
        for (int p = 0; p < 4; ++p) {
            int e  = tid + p * 256;
            int k2 = e >> 6;
            int m2 = (e & 63) << 1;
            ra[p] = *(const uint4*)&A[(size_t)(tile * 16 + k2) * 256 + mb * 128 + m2];
        }
        int k2 = tid >> 4;
        int n4 = (tid & 15) << 2;
        int k0 = tile * 32 + 2 * k2;
        rb0 = *(const float4*)&Bsrc[(size_t)k0 * BT + j0 + n4];
        rb1 = *(const float4*)&Bsrc[(size_t)(k0 + 1) * BT + j0 + n4];
        if (mode == 1) {
            rb0.x = fmaxf(rb0.x, 0.f); rb0.y = fmaxf(rb0.y, 0.f);
            rb0.z = fmaxf(rb0.z, 0.f); rb0.w = fmaxf(rb0.w, 0.f);
            rb1.x = fmaxf(rb1.x, 0.f); rb1.y = fmaxf(rb1.y, 0.f);
            rb1.z = fmaxf(rb1.z, 0.f); rb1.w = fmaxf(rb1.w, 0.f);
        }
    };

    FETCH(0);
    post_sts(S, 0, tid, ra, rb0, rb1);
    __syncthreads();

    const int NT = 8;
    for (int t = 0; t < NT; ++t) {
        if (t + 1 < NT) FETCH(t + 1);
        POST_MMA3(acc, S.A[t & 1], S.B[t & 1], warp_m, warp_n, lane);
        if (t + 1 < NT) post_sts(S, (t + 1) & 1, tid, ra, rb0, rb1);
        __syncthreads();
    }

    int colbase = j0 + warp_n * 16 + (lane & 3) * 2;
    #pragma unroll
    for (int mt = 0; mt < 4; ++mt) {
        int r0 = warp_m * 64 + mt * 16 + (lane >> 2);
        #pragma unroll
        for (int half = 0; half < 2; ++half) {
            int mg = mb * 128 + r0 + half * 8;
            float bv = bias[mg];
            #pragma unroll
            for (int nt = 0; nt < 2; ++nt) {
                float v0 = acc[mt][nt][half * 2 + 0] + bv;
                float v1 = acc[mt][nt][half * 2 + 1] + bv;
                if (mode == 1) { v0 = fmaxf(v0, 0.f); v1 = fmaxf(v1, 0.f); }
                int col = colbase + nt * 8;
                if (mode == 3) {
                    outp[(size_t)(col    ) * NQ + mg] = v0;
                    outp[(size_t)(col + 1) * NQ + mg] = v1;
                } else {
                    float* dst = (mode == 1) ? &d_o1[(size_t)mg * BT + col]
                                             : &d_skip[(size_t)mg * BT + col];
                    *(float2*)dst = make_float2(v0, v1);
                }
            }
        }
    }
}

// =====================================================================
// Launch
// =====================================================================
extern "C" void kernel_launch(void* const* d_in, const int* in_sizes, int n_in,
                              void* d_out, int out_size) {
    const int*   x          = (const int*)  d_in[0];
    const float* h          = (const float*)d_in[1];
    const float* causal_w   = (const float*)d_in[2];
    const float* causal_b   = (const float*)d_in[3];
    const float* dil_sig_w  = (const float*)d_in[4];
    const float* dil_sig_b  = (const float*)d_in[5];
    const float* dil_tanh_w = (const float*)d_in[6];
    const float* dil_tanh_b = (const float*)d_in[7];
    const float* aux_sig_w  = (const float*)d_in[8];
    const float* aux_sig_b  = (const float*)d_in[9];
    const float* aux_tanh_w = (const float*)d_in[10];
    const float* aux_tanh_b = (const float*)d_in[11];
    const float* skip_w     = (const float*)d_in[12];
    const float* skip_b     = (const float*)d_in[13];
    const float* res_w      = (const float*)d_in[14];
    const float* res_b      = (const float*)d_in[15];
    const float* post1_w    = (const float*)d_in[16];
    const float* post1_b    = (const float*)d_in[17];
    const float* post2_w    = (const float*)d_in[18];
    const float* post2_b    = (const float*)d_in[19];
    const float* lin_w      = (const float*)d_in[20];
    const float* lin_b      = (const float*)d_in[21];

    cudaFuncSetAttribute(gate_k,    cudaFuncAttributeMaxDynamicSharedMemorySize, GEMM_SMEM);
    cudaFuncSetAttribute(skipres_k, cudaFuncAttributeMaxDynamicSharedMemorySize, GEMM_SMEM);
    cudaFuncSetAttribute(post_k,    cudaFuncAttributeMaxDynamicSharedMemorySize, POST_SMEM);

    { int n = NLAYERS * 2 * 1024 * 512;       pack_gate_k<<<(n + 255) / 256, 256>>>(dil_sig_w, dil_tanh_w); }
    { int n = NLAYERS * 1024 * 32;            pack_aux_k <<<(n + 255) / 256, 256>>>(aux_sig_w, aux_tanh_w); }
    { int n = NLAYERS * 768 * 512;            pack_rs_k  <<<(n + 255) / 256, 256>>>(skip_w, res_w); }
    { int n = NLAYERS * 1024 + NLAYERS * 768; pack_bias_k<<<(n + 255) / 256, 256>>>(dil_sig_b, dil_tanh_b, aux_sig_b, aux_tanh_b, skip_b, res_b); }
    { int n = 3 * 128 * 256;                  pack_post_k<<<(n + 255) / 256, 256>>>(post1_w, post2_w, lin_w); }

    zero_skip_k<<<(NS * BT + 255) / 256, 256>>>();
    convert_h_k<<<(32 * BT + 255) / 256, 256>>>(h);
    embed_k<<<dim3(BT / 256, NR), 256>>>(x, causal_w, causal_b);

    for (int l = 0; l < NLAYERS; ++l) {
        int d = 1 << (l % 10);
        int useS1 = (d < 8);
        if (useS1) shift_k<<<(NR * BT + 255) / 256, 256>>>(d);
        gate_k   <<<dim3(8, TT / BN, BATCH), NTHREADS, GEMM_SMEM>>>(l, d, useS1);
        skipres_k<<<dim3(6, TT / BN, BATCH), NTHREADS, GEMM_SMEM>>>(l);
    }

    post_k<<<dim3(2, BT / 64), 256, POST_SMEM>>>(1, post1_b, nullptr);
    post_k<<<dim3(2, BT / 64), 256, POST_SMEM>>>(2, post2_b, nullptr);
    post_k<<<dim3(2, BT / 64), 256, POST_SMEM>>>(3, lin_b, (float*)d_out);
}